// round 12
// baseline (speedup 1.0000x reference)
#include <cuda_runtime.h>
#include <cuda_fp16.h>
#include <math.h>

#define NFFT  4096
#define LOGN  12
#define LSEQ  2048
#define BB    32
#define DD    32
#define KK    32
#define OO    32
#define JH    24      // truncated impulse-response length of y-recurrence
#define FH    2064    // padded half-spectrum bin count (>= 2049)
#define TFIX  32      // first TFIX timesteps recomputed exactly (alias reaches t<=22)

// padded shared-FFT addressing
#define PHYS(i) ((i) + ((i) >> 2))
#define FFT_SH  (NFFT + NFFT / 4)   // 5120 float2 = 40 KB

// ---------------- scratch (device globals; no allocation allowed) ------------
__device__ __half2 g_Uh[BB][DD][FH];   // FFT of inputs (fp16)   (b, d, f<=half)
__device__ __half2 g_Gh[BB][OO][FH];   // output spectra (fp16)  (b, o, f<=half)
__device__ __half2 g_Wh[FH][DD][OO];   // combined filter (fp16) (f<=half, d, o)
__device__ float2  g_V[KK][FH];        // FFT of eig_vecs        (k, f<=half)
__device__ float   g_h[JH][OO][OO];    // impulse response of recurrence
__device__ float   g_Fs[TFIX][DD][OO]; // time-domain F for the fixup region
__device__ float2  g_tw[NFFT];         // twiddles, per-stage layout [half + p]

// ---------------- helpers ----------------------------------------------------
__device__ __forceinline__ float2 cmulf(float2 a, float2 b) {
    return make_float2(a.x*b.x - a.y*b.y, a.x*b.y + a.y*b.x);
}

// In-place radix-4 DIT FFT over 4096 complex values in PADDED shared memory
// (element i lives at x[PHYS(i)]). Table-based twiddles. NT = block threads.
template<int NT>
__device__ void fft_shared(float2* x, int inverse) {
    int tid = threadIdx.x;
    __syncthreads();
    if (NT == 1024) {
        #pragma unroll
        for (int k = 0; k < 4; k++) {
            int i = (tid & 3) | (((tid >> 2) & 3) << 8) | (((tid >> 4) & 63) << 2) | (k << 10);
            unsigned r = __brev((unsigned)i) >> 20;
            r = ((r & 0x555u) << 1) | ((r >> 1) & 0x555u);
            if ((unsigned)i < r) {
                float2 t = x[PHYS(i)];
                x[PHYS(i)] = x[PHYS((int)r)];
                x[PHYS((int)r)] = t;
            }
        }
    } else {
        #pragma unroll
        for (int k = 0; k < 8; k++) {
            int i = (tid & 3) | (((tid >> 2) & 3) << 8) | (((tid >> 4) & 31) << 2)
                  | ((k & 1) << 7) | ((k >> 1) << 10);
            unsigned r = __brev((unsigned)i) >> 20;
            r = ((r & 0x555u) << 1) | ((r >> 1) & 0x555u);
            if ((unsigned)i < r) {
                float2 t = x[PHYS(i)];
                x[PHYS(i)] = x[PHYS((int)r)];
                x[PHYS((int)r)] = t;
            }
        }
    }
    __syncthreads();
    #pragma unroll
    for (int rb = 0; rb < 1024 / NT; rb++) {
        float2* xp = x + 5 * (tid + rb * NT);
        float2 A = xp[0], B = xp[1], C = xp[2], D = xp[3];
        float2 t0 = make_float2(A.x + C.x, A.y + C.y);
        float2 t1 = make_float2(A.x - C.x, A.y - C.y);
        float2 t2 = make_float2(B.x + D.x, B.y + D.y);
        float2 t3 = make_float2(B.x - D.x, B.y - D.y);
        float2 y1, y3;
        if (!inverse) {
            y1 = make_float2(t1.x + t3.y, t1.y - t3.x);
            y3 = make_float2(t1.x - t3.y, t1.y + t3.x);
        } else {
            y1 = make_float2(t1.x - t3.y, t1.y + t3.x);
            y3 = make_float2(t1.x + t3.y, t1.y - t3.x);
        }
        xp[0] = make_float2(t0.x + t2.x, t0.y + t2.y);
        xp[1] = y1;
        xp[2] = make_float2(t0.x - t2.x, t0.y - t2.y);
        xp[3] = y3;
    }
    __syncthreads();
    for (int s = 1; s < 6; s++) {
        int q = 1 << (2 * s);
        int stq = q + (q >> 2);
        #pragma unroll
        for (int rb = 0; rb < 1024 / NT; rb++) {
            int bt = tid + rb * NT;
            int p = bt & (q - 1);
            int g = bt >> (2 * s);
            int pb = PHYS((g << (2 * s + 2)) + p);
            float2 w1 = __ldg(&g_tw[2 * q + p]);
            float2 w2 = __ldg(&g_tw[q + p]);
            if (inverse) { w1.y = -w1.y; w2.y = -w2.y; }
            float2 w3 = cmulf(w1, w2);
            float2 A = x[pb];
            float2 B = cmulf(x[pb + stq], w1);
            float2 C = cmulf(x[pb + 2 * stq], w2);
            float2 D = cmulf(x[pb + 3 * stq], w3);
            float2 t0 = make_float2(A.x + C.x, A.y + C.y);
            float2 t1 = make_float2(A.x - C.x, A.y - C.y);
            float2 t2 = make_float2(B.x + D.x, B.y + D.y);
            float2 t3 = make_float2(B.x - D.x, B.y - D.y);
            x[pb]           = make_float2(t0.x + t2.x, t0.y + t2.y);
            x[pb + 2 * stq] = make_float2(t0.x - t2.x, t0.y - t2.y);
            if (!inverse) {
                x[pb + stq]     = make_float2(t1.x + t3.y, t1.y - t3.x);
                x[pb + 3 * stq] = make_float2(t1.x - t3.y, t1.y + t3.x);
            } else {
                x[pb + stq]     = make_float2(t1.x - t3.y, t1.y + t3.x);
                x[pb + 3 * stq] = make_float2(t1.x + t3.y, t1.y - t3.x);
            }
        }
        __syncthreads();
    }
}

// Forward FFT with PRIVATE sincos twiddles (no g_tw dependency) — eig-vec FFTs.
__device__ void fft_shared_sc(float2* x) {
    int tid = threadIdx.x;
    __syncthreads();
    #pragma unroll
    for (int k = 0; k < 4; k++) {
        int i = (tid & 3) | (((tid >> 2) & 3) << 8) | (((tid >> 4) & 63) << 2) | (k << 10);
        unsigned r = __brev((unsigned)i) >> 20;
        r = ((r & 0x555u) << 1) | ((r >> 1) & 0x555u);
        if ((unsigned)i < r) {
            float2 t = x[PHYS(i)];
            x[PHYS(i)] = x[PHYS((int)r)];
            x[PHYS((int)r)] = t;
        }
    }
    __syncthreads();
    {
        float2* xp = x + 5 * tid;
        float2 A = xp[0], B = xp[1], C = xp[2], D = xp[3];
        float2 t0 = make_float2(A.x + C.x, A.y + C.y);
        float2 t1 = make_float2(A.x - C.x, A.y - C.y);
        float2 t2 = make_float2(B.x + D.x, B.y + D.y);
        float2 t3 = make_float2(B.x - D.x, B.y - D.y);
        xp[0] = make_float2(t0.x + t2.x, t0.y + t2.y);
        xp[1] = make_float2(t1.x + t3.y, t1.y - t3.x);
        xp[2] = make_float2(t0.x - t2.x, t0.y - t2.y);
        xp[3] = make_float2(t1.x - t3.y, t1.y + t3.x);
    }
    __syncthreads();
    for (int s = 1; s < 6; s++) {
        int q = 1 << (2 * s);
        int stq = q + (q >> 2);
        int p = tid & (q - 1);
        int g = tid >> (2 * s);
        int pb = PHYS((g << (2 * s + 2)) + p);
        float s1, c1, s2, c2;
        sincosf(-3.14159265358979323846f * (float)p / (float)(2 * q), &s1, &c1);
        sincosf(-3.14159265358979323846f * (float)p / (float)q, &s2, &c2);
        float2 w1 = make_float2(c1, s1);
        float2 w2 = make_float2(c2, s2);
        float2 w3 = cmulf(w1, w2);
        float2 A = x[pb];
        float2 B = cmulf(x[pb + stq], w1);
        float2 C = cmulf(x[pb + 2 * stq], w2);
        float2 D = cmulf(x[pb + 3 * stq], w3);
        float2 t0 = make_float2(A.x + C.x, A.y + C.y);
        float2 t1 = make_float2(A.x - C.x, A.y - C.y);
        float2 t2 = make_float2(B.x + D.x, B.y + D.y);
        float2 t3 = make_float2(B.x - D.x, B.y - D.y);
        x[pb]           = make_float2(t0.x + t2.x, t0.y + t2.y);
        x[pb + 2 * stq] = make_float2(t0.x - t2.x, t0.y - t2.y);
        x[pb + stq]     = make_float2(t1.x + t3.y, t1.y - t3.x);
        x[pb + 3 * stq] = make_float2(t1.x - t3.y, t1.y + t3.x);
        __syncthreads();
    }
}

// ---------------- launch 1: twiddles + h + eig-vec FFTs + Fs -----------------
__global__ void k_pre(const float* __restrict__ m_y,
                      const float* __restrict__ eig_vals,
                      const float* __restrict__ ev,
                      const float* __restrict__ m_phi) {
    __shared__ __align__(16) char raw[FFT_SH * 8];   // 40 KB, reused per role
    int blk = blockIdx.x;
    int tid = threadIdx.x;                  // 1024
    if (blk < 4) {
        int i = blk * 1024 + tid;
        if (i == 0) { g_tw[0] = make_float2(1.f, 0.f); return; }
        int s = 31 - __clz(i);
        int half = 1 << s;
        int p = i - half;
        float ang = -3.14159265358979323846f * (float)p / (float)half;
        float sn, cs; sincosf(ang, &sn, &cs);
        g_tw[i] = make_float2(cs, sn);
    } else if (blk == 4) {
        float* M1  = reinterpret_cast<float*>(raw);
        float* M2  = M1 + OO * OO;
        float* hp  = M2 + OO * OO;
        float* hp2 = hp + OO * OO;
        int o = tid >> 5, i = tid & 31;
        M1[o * 32 + i] = m_y[o * 64 + i];
        M2[o * 32 + i] = m_y[o * 64 + 32 + i];
        float h0 = (o == i) ? 1.f : 0.f;
        hp2[o * 32 + i] = h0;
        g_h[0][o][i] = h0;
        hp[o * 32 + i] = m_y[o * 64 + i];
        g_h[1][o][i] = m_y[o * 64 + i];
        __syncthreads();
        for (int j = 2; j < JH; j++) {
            float acc = 0.f;
            #pragma unroll
            for (int t = 0; t < 32; t++)
                acc += M1[o * 32 + t] * hp[t * 32 + i] + M2[o * 32 + t] * hp2[t * 32 + i];
            __syncthreads();
            hp2[o * 32 + i] = hp[o * 32 + i];
            __syncthreads();
            hp[o * 32 + i] = acc;
            g_h[j][o][i] = acc;
            __syncthreads();
        }
    } else if (blk < 21) {
        float2* sh = reinterpret_cast<float2*>(raw);
        int kp = blk - 5;                   // 0..15 -> filters 2kp, 2kp+1
        for (int t = tid; t < LSEQ; t += 1024) {
            const float2 v = *reinterpret_cast<const float2*>(ev + (size_t)t * KK + 2 * kp);
            sh[PHYS(t)] = v;
        }
        for (int t = LSEQ + tid; t < NFFT; t += 1024) sh[PHYS(t)] = make_float2(0.f, 0.f);
        fft_shared_sc(sh);
        for (int f = tid; f < FH; f += 1024) {
            float2 zf = sh[PHYS(f)];
            int m = (NFFT - f) & (NFFT - 1);
            float2 zm = sh[PHYS(m)];
            g_V[2 * kp][f]     = make_float2(0.5f * (zf.x + zm.x), 0.5f * (zf.y - zm.y));
            g_V[2 * kp + 1][f] = make_float2(0.5f * (zf.y + zm.y), 0.5f * (zm.x - zf.x));
        }
    } else {
        float* sc = reinterpret_cast<float*>(raw);
        float* vv = sc + KK;
        int s = blk - 21;                   // 0..TFIX-1
        if (tid < KK) {
            sc[tid] = sqrtf(sqrtf(eig_vals[tid]));
            vv[tid] = ev[(size_t)s * KK + tid];
        }
        __syncthreads();
        int d = tid >> 5, o = tid & 31;
        float acc = 0.f;
        #pragma unroll
        for (int k = 0; k < KK; k++)
            acc += sc[k] * vv[k] * m_phi[(k * DD + d) * OO + o];
        g_Fs[s][d][o] = acc;
    }
}

// ---------------- launch 2: input FFTs + combined filter W -------------------
__global__ void __launch_bounds__(1024, 2)
k_main(const float* __restrict__ inp,
       const float* __restrict__ eig_vals,
       const float* __restrict__ m_phi,
       const float* __restrict__ m_u) {
    __shared__ __align__(16) char raw[FFT_SH * 8];   // 40 KB
    int blk = blockIdx.x;
    int tid = threadIdx.x;                  // 1024
    if (blk < 512) {
        float2* sh = reinterpret_cast<float2*>(raw);
        int b = blk >> 4, dp = blk & 15;
        for (int t = tid; t < LSEQ; t += 1024) {
            const float2 v = *reinterpret_cast<const float2*>(
                inp + ((size_t)(b * LSEQ + t)) * DD + 2 * dp);
            sh[PHYS(t)] = v;
        }
        for (int t = LSEQ + tid; t < NFFT; t += 1024) sh[PHYS(t)] = make_float2(0.f, 0.f);
        fft_shared<1024>(sh, 0);
        for (int f = tid; f < FH; f += 1024) {
            float2 zf = sh[PHYS(f)];
            int m = (NFFT - f) & (NFFT - 1);
            float2 zm = sh[PHYS(m)];
            g_Uh[b][2 * dp][f]     = __floats2half2_rn(0.5f * (zf.x + zm.x), 0.5f * (zf.y - zm.y));
            g_Uh[b][2 * dp + 1][f] = __floats2half2_rn(0.5f * (zf.y + zm.y), 0.5f * (zm.x - zf.x));
        }
    } else {
        float2 (*Hs)[OO][OO + 1] = reinterpret_cast<float2(*)[OO][OO + 1]>(raw);
        float2 (*FAs)[DD][OO]    = reinterpret_cast<float2(*)[DD][OO]>(raw + 16896);
        float2 (*sv)[KK]         = reinterpret_cast<float2(*)[KK]>(raw + 33280);
        float2 (*wpre)[JH]       = reinterpret_cast<float2(*)[JH]>(raw + 33792);
        int f0 = (blk - 512) * 2;
        int o = tid >> 5, i = tid & 31;

        if (tid < 2 * JH) {
            int bin = tid >= JH ? 1 : 0;
            int j = tid - bin * JH;
            float ang = -6.283185307179586f * (float)(f0 + bin) * (float)j / (float)NFFT;
            float sn, cs; sincosf(ang, &sn, &cs);
            wpre[bin][j] = make_float2(cs, sn);
        }
        if (tid >= 64 && tid < 128) {
            int bin = (tid - 64) >> 5, k = tid & 31;
            float sc = sqrtf(sqrtf(eig_vals[k]));
            float2 v = g_V[k][f0 + bin];
            sv[bin][k] = make_float2(v.x * sc, v.y * sc);
        }
        __syncthreads();

        float2 acc0 = make_float2(0.f, 0.f), acc1 = acc0;
        #pragma unroll 4
        for (int j = 0; j < JH; j++) {
            float hv = g_h[j][o][i];
            float2 w0j = wpre[0][j];
            float2 w1j = wpre[1][j];
            acc0.x += hv * w0j.x; acc0.y += hv * w0j.y;
            acc1.x += hv * w1j.x; acc1.y += hv * w1j.y;
        }
        Hs[0][i][o] = acc0;
        Hs[1][i][o] = acc1;

        int d = o, q = i;
        float2 fa0 = make_float2(0.f, 0.f), fa1 = fa0;
        #pragma unroll 8
        for (int k = 0; k < KK; k++) {
            float m = m_phi[(k * DD + d) * OO + q];
            fa0.x += sv[0][k].x * m; fa0.y += sv[0][k].y * m;
            fa1.x += sv[1][k].x * m; fa1.y += sv[1][k].y * m;
        }
        float a0 = m_u[(q * DD + d) * 3 + 0];
        float a1 = m_u[(q * DD + d) * 3 + 1];
        float a2 = m_u[(q * DD + d) * 3 + 2];
        {
            float2 e1 = wpre[0][1], e2 = wpre[0][2];
            fa0.x += a0 + a1 * e1.x + a2 * e2.x;
            fa0.y += a1 * e1.y + a2 * e2.y;
        }
        {
            float2 e1 = wpre[1][1], e2 = wpre[1][2];
            fa1.x += a0 + a1 * e1.x + a2 * e2.x;
            fa1.y += a1 * e1.y + a2 * e2.y;
        }
        FAs[0][d][q] = fa0;
        FAs[1][d][q] = fa1;
        __syncthreads();

        float2 r0 = make_float2(0.f, 0.f), r1 = r0;
        #pragma unroll 8
        for (int t = 0; t < OO; t++) {
            float2 A = FAs[0][d][t];
            float2 h = Hs[0][t][i];
            r0.x += A.x * h.x - A.y * h.y;
            r0.y += A.x * h.y + A.y * h.x;
            float2 B = FAs[1][d][t];
            float2 g = Hs[1][t][i];
            r1.x += B.x * g.x - B.y * g.y;
            r1.y += B.x * g.y + B.y * g.x;
        }
        g_Wh[f0][d][i]     = __floats2half2_rn(r0.x, r0.y);
        g_Wh[f0 + 1][d][i] = __floats2half2_rn(r1.x, r1.y);
    }
}

// ---------------- launch 3: fix (blocks 0..31) + k_mul (blocks 32..547) ------
// fix depends only on g_Fs/inp (launch 1); mul reads g_Uh/g_Wh (launch 2);
// they share a grid so the fix cost hides inside mul's wave.
__global__ void k_mulfix(const float* __restrict__ inp,
                         const float* __restrict__ m_u,
                         const float* __restrict__ m_y,
                         float* __restrict__ out) {
    __shared__ __align__(16) char raw[BB * 4 * (DD + 2) * 8];   // 34.8 KB union
    int blk = blockIdx.x;
    int tid = threadIdx.x;                  // 256
    if (blk >= BB) {
        // ---- k_mul role ----
        float2 (*Us)[4][DD + 2] = reinterpret_cast<float2(*)[4][DD + 2]>(raw);
        int f0 = (blk - BB) * 4;
        #pragma unroll
        for (int k = 0; k < 4; k++) {
            int pair = tid + k * 256;
            int b = pair >> 5, d = pair & 31;
            uint4 rw = *reinterpret_cast<const uint4*>(&g_Uh[b][d][f0]);
            __half2 h0 = *reinterpret_cast<__half2*>(&rw.x);
            __half2 h1 = *reinterpret_cast<__half2*>(&rw.y);
            __half2 h2 = *reinterpret_cast<__half2*>(&rw.z);
            __half2 h3 = *reinterpret_cast<__half2*>(&rw.w);
            Us[b][0][d] = __half22float2(h0);
            Us[b][1][d] = __half22float2(h1);
            Us[b][2][d] = __half22float2(h2);
            Us[b][3][d] = __half22float2(h3);
        }
        int bh = tid >> 7;
        int o  = (tid >> 2) & 31;
        int fi = tid & 3;
        int f  = f0 + fi;
        float2 Wreg[DD];
        #pragma unroll
        for (int d = 0; d < DD; d++) Wreg[d] = __half22float2(g_Wh[f][d][o]);
        __syncthreads();
        for (int bi = 0; bi < 16; bi++) {
            int b = bh * 16 + bi;
            float2 a0 = make_float2(0.f, 0.f), a1 = a0;
            const float4* up = reinterpret_cast<const float4*>(&Us[b][fi][0]);
            #pragma unroll
            for (int d2 = 0; d2 < DD / 2; d2++) {
                float4 uv = up[d2];
                float2 w0 = Wreg[2 * d2], w1 = Wreg[2 * d2 + 1];
                a0.x += uv.x * w0.x - uv.y * w0.y;
                a0.y += uv.x * w0.y + uv.y * w0.x;
                a1.x += uv.z * w1.x - uv.w * w1.y;
                a1.y += uv.z * w1.y + uv.w * w1.x;
            }
            g_Gh[b][o][f] = __floats2half2_rn(a0.x + a1.x, a0.y + a1.y);
        }
    } else {
        // ---- fix role: exact recompute of y for t < TFIX, batch b = blk ----
        float* u     = reinterpret_cast<float*>(raw);            // 1024 f
        float* Fsh   = u + TFIX * DD;                            // 1024 f
        float* delta = Fsh + DD * OO;                            // 1024 f
        float* M1t   = delta + TFIX * OO;                        // 1024 f  (M1t[i*32+o] = m_y[o*64+i])
        float* M2t   = M1t + OO * OO;                            // 1024 f
        float* y1    = M2t + OO * OO;                            // 32 f
        float* y2    = y1 + OO;                                  // 32 f
        int b = blk;
        for (int idx = tid; idx < TFIX * DD; idx += 256)
            u[idx] = inp[(size_t)b * LSEQ * DD + idx];
        for (int idx = tid; idx < OO * OO; idx += 256) {
            int i = idx >> 5, o = idx & 31;
            M1t[i * 32 + o] = m_y[o * 64 + i];
            M2t[i * 32 + o] = m_y[o * 64 + 32 + i];
        }
        __syncthreads();
        float acc[4];
        #pragma unroll
        for (int r = 0; r < 4; r++) {
            int idx = tid + r * 256;
            int t = idx >> 5, o = idx & 31;
            float a = 0.f;
            for (int j = 0; j < 3; j++) {
                if (t >= j) {
                    #pragma unroll
                    for (int i = 0; i < DD; i++)
                        a += m_u[(o * DD + i) * 3 + j] * u[(t - j) * DD + i];
                }
            }
            acc[r] = a;
        }
        for (int s = 0; s < TFIX; s++) {
            const float* fp = &g_Fs[s][0][0];
            for (int idx = tid; idx < DD * OO; idx += 256) Fsh[idx] = fp[idx];
            __syncthreads();
            #pragma unroll
            for (int r = 0; r < 4; r++) {
                int idx = tid + r * 256;
                int t = idx >> 5, o = idx & 31;
                if (t >= s) {
                    float a = acc[r];
                    const float* ur = &u[(t - s) * DD];
                    #pragma unroll
                    for (int d = 0; d < DD; d++)
                        a += ur[d] * Fsh[d * OO + o];
                    acc[r] = a;
                }
            }
            __syncthreads();
        }
        #pragma unroll
        for (int r = 0; r < 4; r++) { int idx = tid + r * 256; delta[idx] = acc[r]; }
        __syncthreads();
        if (tid < OO) {
            int o = tid;
            y1[o] = 0.f; y2[o] = 0.f;
            __syncwarp();
            for (int t = 0; t < TFIX; t++) {
                float a = delta[t * OO + o];
                #pragma unroll
                for (int i = 0; i < OO; i++)
                    a += M1t[i * 32 + o] * y1[i] + M2t[i * 32 + o] * y2[i];
                __syncwarp();
                y2[o] = y1[o];
                __syncwarp();
                y1[o] = a;
                __syncwarp();
                out[((size_t)(b * LSEQ + t)) * OO + o] = a;
            }
        }
    }
}

// ---------------- launch 4: inverse FFT (standalone; profiled) ---------------
__global__ void k_ifft(float* __restrict__ out) {
    __shared__ __align__(16) float2 sh[FFT_SH];
    int blk = blockIdx.x;                   // 512: (b, opair)
    int b = blk >> 4, op = blk & 15;
    int tid = threadIdx.x;                  // 512
    #pragma unroll
    for (int rr = 0; rr < 4; rr++) {
        int f = tid + rr * 512;             // 0..2047
        float2 a = __half22float2(g_Gh[b][2 * op][f]);
        float2 c = __half22float2(g_Gh[b][2 * op + 1][f]);
        sh[PHYS(f)] = make_float2(a.x - c.y, a.y + c.x);
        if (f > 0)
            sh[PHYS(NFFT - f)] = make_float2(a.x + c.y, c.x - a.y);
    }
    if (tid == 0) {
        float2 a = __half22float2(g_Gh[b][2 * op][2048]);
        float2 c = __half22float2(g_Gh[b][2 * op + 1][2048]);
        sh[PHYS(2048)] = make_float2(a.x - c.y, a.y + c.x);
    }
    fft_shared<512>(sh, 1);
    const float inv = 1.f / (float)NFFT;
    for (int t = tid; t < LSEQ; t += 512) {
        if (t < TFIX) continue;             // fix (launch 3) owns these
        float2 z = sh[PHYS(t)];
        float2* p = reinterpret_cast<float2*>(out + ((size_t)(b * LSEQ + t)) * OO + 2 * op);
        *p = make_float2(z.x * inv, z.y * inv);
    }
}

// ---------------- launch ------------------------------------------------------
extern "C" void kernel_launch(void* const* d_in, const int* in_sizes, int n_in,
                              void* d_out, int out_size) {
    const float* inputs  = (const float*)d_in[0];
    const float* eigvals = (const float*)d_in[1];
    const float* eigvecs = (const float*)d_in[2];
    const float* m_u     = (const float*)d_in[3];
    const float* m_phi   = (const float*)d_in[4];
    const float* m_y     = (const float*)d_in[5];
    float* out = (float*)d_out;

    k_pre    <<<53, 1024>>>(m_y, eigvals, eigvecs, m_phi);          // launch 1
    k_main   <<<512 + FH / 2, 1024>>>(inputs, eigvals, m_phi, m_u); // launch 2
    k_mulfix <<<BB + FH / 4, 256>>>(inputs, m_u, m_y, out);         // launch 3
    k_ifft   <<<BB * OO / 2, 512>>>(out);                           // launch 4 (profiled)
}

// round 14
// speedup vs baseline: 1.0579x; 1.0579x over previous
#include <cuda_runtime.h>
#include <cuda_fp16.h>
#include <math.h>

#define NFFT  4096
#define LOGN  12
#define LSEQ  2048
#define BB    32
#define DD    32
#define KK    32
#define OO    32
#define JH    24      // truncated impulse-response length of y-recurrence
#define FH    2064    // padded half-spectrum bin count (>= 2049)
#define TFIX  32      // first TFIX timesteps recomputed exactly (alias reaches t<=22)

// padded shared-FFT addressing
#define PHYS(i) ((i) + ((i) >> 2))
#define FFT_SH  (NFFT + NFFT / 4)   // 5120 float2 = 40 KB

// ---------------- scratch (device globals; no allocation allowed) ------------
__device__ __half2 g_Uh[BB][DD][FH];   // FFT of inputs (fp16)   (b, d, f<=half)
__device__ __half2 g_Gh[BB][OO][FH];   // output spectra (fp16)  (b, o, f<=half)
__device__ __half2 g_Wh[FH][DD][OO];   // combined filter (fp16) (f<=half, d, o)
__device__ float2  g_V[KK][FH];        // FFT of eig_vecs        (k, f<=half)
__device__ float   g_h[JH][OO][OO];    // impulse response of recurrence
__device__ float   g_Fs[TFIX][DD][OO]; // time-domain F for the fixup region
__device__ float2  g_tw[NFFT];         // twiddles, per-stage layout [half + p]

// ---------------- helpers ----------------------------------------------------
__device__ __forceinline__ float2 cmulf(float2 a, float2 b) {
    return make_float2(a.x*b.x - a.y*b.y, a.x*b.y + a.y*b.x);
}

__device__ __forceinline__ void bfly4(float2& A, float2& B, float2& C, float2& D,
                                      int inverse) {
    float2 t0 = make_float2(A.x + C.x, A.y + C.y);
    float2 t1 = make_float2(A.x - C.x, A.y - C.y);
    float2 t2 = make_float2(B.x + D.x, B.y + D.y);
    float2 t3 = make_float2(B.x - D.x, B.y - D.y);
    A = make_float2(t0.x + t2.x, t0.y + t2.y);
    C = make_float2(t0.x - t2.x, t0.y - t2.y);
    if (!inverse) {
        B = make_float2(t1.x + t3.y, t1.y - t3.x);
        D = make_float2(t1.x - t3.y, t1.y + t3.x);
    } else {
        B = make_float2(t1.x - t3.y, t1.y + t3.x);
        D = make_float2(t1.x + t3.y, t1.y - t3.x);
    }
}

// Radix-16 FFT over 4096 complex values in PADDED shared memory (element i at
// x[PHYS(i)], written in NATURAL order by the caller). 256 threads; 16 elements
// per thread; 3 shared rounds (two radix-4 stages fused in registers each);
// digit-reversal folded into the first pair's gather. The __syncthreads()
// between the gather and the scatter in pair 0 is load-bearing: the gather is
// scattered across the whole array while the scatter is contiguous per thread.
// inverse=1: conjugated twiddles (caller scales by 1/N).
__device__ void fft16(float2* x, int inverse) {
    int tid = threadIdx.x;   // 256
    __syncthreads();
    // ---- pair 0: stages q=1 and q=4; reads digit-reversed, writes 16t+j ----
    {
        int revT = ((tid & 3) << 6) | (((tid >> 2) & 3) << 4)
                 | (((tid >> 4) & 3) << 2) | ((tid >> 6) & 3);
        float2 v[16];
        #pragma unroll
        for (int j = 0; j < 16; j++) {
            int src = revT + ((j >> 2) << 8) + ((j & 3) << 10);
            v[j] = x[PHYS(src)];
        }
        __syncthreads();   // ALL gathers complete before ANY scatter (race fix)
        // stage q=1: twiddles are exactly 1
        #pragma unroll
        for (int c = 0; c < 4; c++)
            bfly4(v[4*c], v[4*c+1], v[4*c+2], v[4*c+3], inverse);
        // stage q=4: twiddle index = c
        #pragma unroll
        for (int c = 0; c < 4; c++) {
            float2 w1 = __ldg(&g_tw[8 + c]);
            float2 w2 = __ldg(&g_tw[4 + c]);
            if (inverse) { w1.y = -w1.y; w2.y = -w2.y; }
            float2 w3 = cmulf(w1, w2);
            v[c+4]  = cmulf(v[c+4],  w1);
            v[c+8]  = cmulf(v[c+8],  w2);
            v[c+12] = cmulf(v[c+12], w3);
            bfly4(v[c], v[c+4], v[c+8], v[c+12], inverse);
        }
        int base = tid << 4;
        #pragma unroll
        for (int j = 0; j < 16; j++) x[PHYS(base + j)] = v[j];
    }
    __syncthreads();
    // ---- pair 1: stages q=16 and q=64 (per-thread positions: no race) ------
    {
        int p = tid & 15;
        int base = ((tid >> 4) << 8) | p;
        float2 v[16];
        #pragma unroll
        for (int j = 0; j < 16; j++) v[j] = x[PHYS(base + j * 16)];
        float2 w1 = __ldg(&g_tw[32 + p]);
        float2 w2 = __ldg(&g_tw[16 + p]);
        if (inverse) { w1.y = -w1.y; w2.y = -w2.y; }
        float2 w3 = cmulf(w1, w2);
        #pragma unroll
        for (int c = 0; c < 4; c++) {
            v[4*c+1] = cmulf(v[4*c+1], w1);
            v[4*c+2] = cmulf(v[4*c+2], w2);
            v[4*c+3] = cmulf(v[4*c+3], w3);
            bfly4(v[4*c], v[4*c+1], v[4*c+2], v[4*c+3], inverse);
        }
        #pragma unroll
        for (int c = 0; c < 4; c++) {
            int pc = p + c * 16;
            float2 u1 = __ldg(&g_tw[128 + pc]);
            float2 u2 = __ldg(&g_tw[64 + pc]);
            if (inverse) { u1.y = -u1.y; u2.y = -u2.y; }
            float2 u3 = cmulf(u1, u2);
            v[c+4]  = cmulf(v[c+4],  u1);
            v[c+8]  = cmulf(v[c+8],  u2);
            v[c+12] = cmulf(v[c+12], u3);
            bfly4(v[c], v[c+4], v[c+8], v[c+12], inverse);
        }
        #pragma unroll
        for (int j = 0; j < 16; j++) x[PHYS(base + j * 16)] = v[j];
    }
    __syncthreads();
    // ---- pair 2: stages q=256 and q=1024 ------------------------------------
    {
        int p = tid;
        float2 v[16];
        #pragma unroll
        for (int j = 0; j < 16; j++) v[j] = x[PHYS(p + j * 256)];
        float2 w1 = __ldg(&g_tw[512 + p]);
        float2 w2 = __ldg(&g_tw[256 + p]);
        if (inverse) { w1.y = -w1.y; w2.y = -w2.y; }
        float2 w3 = cmulf(w1, w2);
        #pragma unroll
        for (int c = 0; c < 4; c++) {
            v[4*c+1] = cmulf(v[4*c+1], w1);
            v[4*c+2] = cmulf(v[4*c+2], w2);
            v[4*c+3] = cmulf(v[4*c+3], w3);
            bfly4(v[4*c], v[4*c+1], v[4*c+2], v[4*c+3], inverse);
        }
        #pragma unroll
        for (int c = 0; c < 4; c++) {
            int pc = p + c * 256;
            float2 u1 = __ldg(&g_tw[2048 + pc]);
            float2 u2 = __ldg(&g_tw[1024 + pc]);
            if (inverse) { u1.y = -u1.y; u2.y = -u2.y; }
            float2 u3 = cmulf(u1, u2);
            v[c+4]  = cmulf(v[c+4],  u1);
            v[c+8]  = cmulf(v[c+8],  u2);
            v[c+12] = cmulf(v[c+12], u3);
            bfly4(v[c], v[c+4], v[c+8], v[c+12], inverse);
        }
        #pragma unroll
        for (int j = 0; j < 16; j++) x[PHYS(p + j * 256)] = v[j];
    }
    __syncthreads();
}

// Forward FFT with PRIVATE sincos twiddles (no g_tw dependency) — eig-vec FFT
// blocks inside k_pre (same launch computes g_tw, so the table can't be used).
__device__ void fft_shared_sc(float2* x) {
    int tid = threadIdx.x;                  // 1024
    __syncthreads();
    #pragma unroll
    for (int k = 0; k < 4; k++) {
        int i = (tid & 3) | (((tid >> 2) & 3) << 8) | (((tid >> 4) & 63) << 2) | (k << 10);
        unsigned r = __brev((unsigned)i) >> 20;
        r = ((r & 0x555u) << 1) | ((r >> 1) & 0x555u);
        if ((unsigned)i < r) {
            float2 t = x[PHYS(i)];
            x[PHYS(i)] = x[PHYS((int)r)];
            x[PHYS((int)r)] = t;
        }
    }
    __syncthreads();
    {
        float2* xp = x + 5 * tid;
        float2 A = xp[0], B = xp[1], C = xp[2], D = xp[3];
        bfly4(A, B, C, D, 0);
        xp[0] = A; xp[1] = B; xp[2] = C; xp[3] = D;
    }
    __syncthreads();
    for (int s = 1; s < 6; s++) {
        int q = 1 << (2 * s);
        int stq = q + (q >> 2);
        int p = tid & (q - 1);
        int g = tid >> (2 * s);
        int pb = PHYS((g << (2 * s + 2)) + p);
        float s1, c1, s2, c2;
        sincosf(-3.14159265358979323846f * (float)p / (float)(2 * q), &s1, &c1);
        sincosf(-3.14159265358979323846f * (float)p / (float)q, &s2, &c2);
        float2 w1 = make_float2(c1, s1);
        float2 w2 = make_float2(c2, s2);
        float2 w3 = cmulf(w1, w2);
        float2 A = x[pb];
        float2 B = cmulf(x[pb + stq], w1);
        float2 C = cmulf(x[pb + 2 * stq], w2);
        float2 D = cmulf(x[pb + 3 * stq], w3);
        bfly4(A, B, C, D, 0);
        x[pb] = A; x[pb + stq] = B; x[pb + 2 * stq] = C; x[pb + 3 * stq] = D;
        __syncthreads();
    }
}

// ---------------- launch 1: twiddles + h + eig-vec FFTs + Fs -----------------
__global__ void k_pre(const float* __restrict__ m_y,
                      const float* __restrict__ eig_vals,
                      const float* __restrict__ ev,
                      const float* __restrict__ m_phi) {
    __shared__ __align__(16) char raw[FFT_SH * 8];   // 40 KB, reused per role
    int blk = blockIdx.x;
    int tid = threadIdx.x;                  // 1024
    if (blk < 4) {
        int i = blk * 1024 + tid;
        if (i == 0) { g_tw[0] = make_float2(1.f, 0.f); return; }
        int s = 31 - __clz(i);
        int half = 1 << s;
        int p = i - half;
        float ang = -3.14159265358979323846f * (float)p / (float)half;
        float sn, cs; sincosf(ang, &sn, &cs);
        g_tw[i] = make_float2(cs, sn);
    } else if (blk == 4) {
        float* M1  = reinterpret_cast<float*>(raw);
        float* M2  = M1 + OO * OO;
        float* hp  = M2 + OO * OO;
        float* hp2 = hp + OO * OO;
        int o = tid >> 5, i = tid & 31;
        M1[o * 32 + i] = m_y[o * 64 + i];
        M2[o * 32 + i] = m_y[o * 64 + 32 + i];
        float h0 = (o == i) ? 1.f : 0.f;
        hp2[o * 32 + i] = h0;
        g_h[0][o][i] = h0;
        hp[o * 32 + i] = m_y[o * 64 + i];
        g_h[1][o][i] = m_y[o * 64 + i];
        __syncthreads();
        for (int j = 2; j < JH; j++) {
            float acc = 0.f;
            #pragma unroll
            for (int t = 0; t < 32; t++)
                acc += M1[o * 32 + t] * hp[t * 32 + i] + M2[o * 32 + t] * hp2[t * 32 + i];
            __syncthreads();
            hp2[o * 32 + i] = hp[o * 32 + i];
            __syncthreads();
            hp[o * 32 + i] = acc;
            g_h[j][o][i] = acc;
            __syncthreads();
        }
    } else if (blk < 21) {
        float2* sh = reinterpret_cast<float2*>(raw);
        int kp = blk - 5;                   // 0..15 -> filters 2kp, 2kp+1
        for (int t = tid; t < LSEQ; t += 1024) {
            const float2 v = *reinterpret_cast<const float2*>(ev + (size_t)t * KK + 2 * kp);
            sh[PHYS(t)] = v;
        }
        for (int t = LSEQ + tid; t < NFFT; t += 1024) sh[PHYS(t)] = make_float2(0.f, 0.f);
        fft_shared_sc(sh);
        for (int f = tid; f < FH; f += 1024) {
            float2 zf = sh[PHYS(f)];
            int m = (NFFT - f) & (NFFT - 1);
            float2 zm = sh[PHYS(m)];
            g_V[2 * kp][f]     = make_float2(0.5f * (zf.x + zm.x), 0.5f * (zf.y - zm.y));
            g_V[2 * kp + 1][f] = make_float2(0.5f * (zf.y + zm.y), 0.5f * (zm.x - zf.x));
        }
    } else {
        float* sc = reinterpret_cast<float*>(raw);
        float* vv = sc + KK;
        int s = blk - 21;                   // 0..TFIX-1
        if (tid < KK) {
            sc[tid] = sqrtf(sqrtf(eig_vals[tid]));
            vv[tid] = ev[(size_t)s * KK + tid];
        }
        __syncthreads();
        int d = tid >> 5, o = tid & 31;
        float acc = 0.f;
        #pragma unroll
        for (int k = 0; k < KK; k++)
            acc += sc[k] * vv[k] * m_phi[(k * DD + d) * OO + o];
        g_Fs[s][d][o] = acc;
    }
}

// ---------------- launch 2: forward FFTs of inputs (radix-16, 256 thr) -------
__global__ void k_fwd(const float* __restrict__ inp) {
    __shared__ __align__(16) float2 sh[FFT_SH];
    int blk = blockIdx.x;                   // 512: (b, dpair)
    int b = blk >> 4, dp = blk & 15;
    int tid = threadIdx.x;                  // 256
    #pragma unroll
    for (int rr = 0; rr < 8; rr++) {
        int t = tid + rr * 256;
        const float2 v = *reinterpret_cast<const float2*>(
            inp + ((size_t)(b * LSEQ + t)) * DD + 2 * dp);
        sh[PHYS(t)] = v;
    }
    #pragma unroll
    for (int rr = 0; rr < 8; rr++) {
        int t = LSEQ + tid + rr * 256;
        sh[PHYS(t)] = make_float2(0.f, 0.f);
    }
    fft16(sh, 0);
    for (int f = tid; f < FH; f += 256) {
        float2 zf = sh[PHYS(f)];
        int m = (NFFT - f) & (NFFT - 1);
        float2 zm = sh[PHYS(m)];
        g_Uh[b][2 * dp][f]     = __floats2half2_rn(0.5f * (zf.x + zm.x), 0.5f * (zf.y - zm.y));
        g_Uh[b][2 * dp + 1][f] = __floats2half2_rn(0.5f * (zf.y + zm.y), 0.5f * (zm.x - zf.x));
    }
}

// ---------------- launch 3: fused combined filter W (2 bins / block) ---------
__global__ void k_W(const float* __restrict__ eig_vals,
                    const float* __restrict__ m_phi,
                    const float* __restrict__ m_u) {
    __shared__ float2 Hs[2][OO][OO + 1];    // transposed: Hs[bin][o'][o]
    __shared__ float2 FAs[2][DD][OO];
    __shared__ float2 sv[2][KK];
    __shared__ float2 wpre[2][JH];          // e^{-i 2pi f j / N}
    int f0 = blockIdx.x * 2;
    int tid = threadIdx.x;                  // 1024
    int o = tid >> 5, i = tid & 31;

    if (tid < 2 * JH) {
        int bin = tid >= JH ? 1 : 0;
        int j = tid - bin * JH;
        float ang = -6.283185307179586f * (float)(f0 + bin) * (float)j / (float)NFFT;
        float sn, cs; sincosf(ang, &sn, &cs);
        wpre[bin][j] = make_float2(cs, sn);
    }
    if (tid >= 64 && tid < 128) {
        int bin = (tid - 64) >> 5, k = tid & 31;
        float sc = sqrtf(sqrtf(eig_vals[k]));
        float2 v = g_V[k][f0 + bin];
        sv[bin][k] = make_float2(v.x * sc, v.y * sc);
    }
    __syncthreads();

    float2 acc0 = make_float2(0.f, 0.f), acc1 = acc0;
    #pragma unroll 4
    for (int j = 0; j < JH; j++) {
        float hv = g_h[j][o][i];
        float2 w0j = wpre[0][j];
        float2 w1j = wpre[1][j];
        acc0.x += hv * w0j.x; acc0.y += hv * w0j.y;
        acc1.x += hv * w1j.x; acc1.y += hv * w1j.y;
    }
    Hs[0][i][o] = acc0;
    Hs[1][i][o] = acc1;

    int d = o, q = i;
    float2 fa0 = make_float2(0.f, 0.f), fa1 = fa0;
    #pragma unroll 8
    for (int k = 0; k < KK; k++) {
        float m = m_phi[(k * DD + d) * OO + q];
        fa0.x += sv[0][k].x * m; fa0.y += sv[0][k].y * m;
        fa1.x += sv[1][k].x * m; fa1.y += sv[1][k].y * m;
    }
    float a0 = m_u[(q * DD + d) * 3 + 0];
    float a1 = m_u[(q * DD + d) * 3 + 1];
    float a2 = m_u[(q * DD + d) * 3 + 2];
    {
        float2 e1 = wpre[0][1], e2 = wpre[0][2];
        fa0.x += a0 + a1 * e1.x + a2 * e2.x;
        fa0.y += a1 * e1.y + a2 * e2.y;
    }
    {
        float2 e1 = wpre[1][1], e2 = wpre[1][2];
        fa1.x += a0 + a1 * e1.x + a2 * e2.x;
        fa1.y += a1 * e1.y + a2 * e2.y;
    }
    FAs[0][d][q] = fa0;
    FAs[1][d][q] = fa1;
    __syncthreads();

    float2 r0 = make_float2(0.f, 0.f), r1 = r0;
    #pragma unroll 8
    for (int t = 0; t < OO; t++) {
        float2 A = FAs[0][d][t];
        float2 h = Hs[0][t][i];
        r0.x += A.x * h.x - A.y * h.y;
        r0.y += A.x * h.y + A.y * h.x;
        float2 B = FAs[1][d][t];
        float2 g = Hs[1][t][i];
        r1.x += B.x * g.x - B.y * g.y;
        r1.y += B.x * g.y + B.y * g.x;
    }
    g_Wh[f0][d][i]     = __floats2half2_rn(r0.x, r0.y);
    g_Wh[f0 + 1][d][i] = __floats2half2_rn(r1.x, r1.y);
}

// ---------------- launch 4: fix (blocks 0..31) + k_mul (blocks 32..547) ------
__global__ void k_mulfix(const float* __restrict__ inp,
                         const float* __restrict__ m_u,
                         const float* __restrict__ m_y,
                         float* __restrict__ out) {
    __shared__ __align__(16) char raw[BB * 4 * (DD + 2) * 8];   // 34.8 KB union
    int blk = blockIdx.x;
    int tid = threadIdx.x;                  // 256
    if (blk >= BB) {
        float2 (*Us)[4][DD + 2] = reinterpret_cast<float2(*)[4][DD + 2]>(raw);
        int f0 = (blk - BB) * 4;
        #pragma unroll
        for (int k = 0; k < 4; k++) {
            int pair = tid + k * 256;
            int b = pair >> 5, d = pair & 31;
            uint4 rw = *reinterpret_cast<const uint4*>(&g_Uh[b][d][f0]);
            __half2 h0 = *reinterpret_cast<__half2*>(&rw.x);
            __half2 h1 = *reinterpret_cast<__half2*>(&rw.y);
            __half2 h2 = *reinterpret_cast<__half2*>(&rw.z);
            __half2 h3 = *reinterpret_cast<__half2*>(&rw.w);
            Us[b][0][d] = __half22float2(h0);
            Us[b][1][d] = __half22float2(h1);
            Us[b][2][d] = __half22float2(h2);
            Us[b][3][d] = __half22float2(h3);
        }
        int bh = tid >> 7;
        int o  = (tid >> 2) & 31;
        int fi = tid & 3;
        int f  = f0 + fi;
        float2 Wreg[DD];
        #pragma unroll
        for (int d = 0; d < DD; d++) Wreg[d] = __half22float2(g_Wh[f][d][o]);
        __syncthreads();
        for (int bi = 0; bi < 16; bi++) {
            int b = bh * 16 + bi;
            float2 a0 = make_float2(0.f, 0.f), a1 = a0;
            const float4* up = reinterpret_cast<const float4*>(&Us[b][fi][0]);
            #pragma unroll
            for (int d2 = 0; d2 < DD / 2; d2++) {
                float4 uv = up[d2];
                float2 w0 = Wreg[2 * d2], w1 = Wreg[2 * d2 + 1];
                a0.x += uv.x * w0.x - uv.y * w0.y;
                a0.y += uv.x * w0.y + uv.y * w0.x;
                a1.x += uv.z * w1.x - uv.w * w1.y;
                a1.y += uv.z * w1.y + uv.w * w1.x;
            }
            g_Gh[b][o][f] = __floats2half2_rn(a0.x + a1.x, a0.y + a1.y);
        }
    } else {
        float* u     = reinterpret_cast<float*>(raw);            // 1024 f
        float* Fsh   = u + TFIX * DD;                            // 1024 f
        float* delta = Fsh + DD * OO;                            // 1024 f
        float* M1t   = delta + TFIX * OO;                        // 1024 f
        float* M2t   = M1t + OO * OO;                            // 1024 f
        float* y1    = M2t + OO * OO;                            // 32 f
        float* y2    = y1 + OO;                                  // 32 f
        int b = blk;
        for (int idx = tid; idx < TFIX * DD; idx += 256)
            u[idx] = inp[(size_t)b * LSEQ * DD + idx];
        for (int idx = tid; idx < OO * OO; idx += 256) {
            int i = idx >> 5, o = idx & 31;
            M1t[i * 32 + o] = m_y[o * 64 + i];
            M2t[i * 32 + o] = m_y[o * 64 + 32 + i];
        }
        __syncthreads();
        float acc[4];
        #pragma unroll
        for (int r = 0; r < 4; r++) {
            int idx = tid + r * 256;
            int t = idx >> 5, o = idx & 31;
            float a = 0.f;
            for (int j = 0; j < 3; j++) {
                if (t >= j) {
                    #pragma unroll
                    for (int i = 0; i < DD; i++)
                        a += m_u[(o * DD + i) * 3 + j] * u[(t - j) * DD + i];
                }
            }
            acc[r] = a;
        }
        for (int s = 0; s < TFIX; s++) {
            const float* fp = &g_Fs[s][0][0];
            for (int idx = tid; idx < DD * OO; idx += 256) Fsh[idx] = fp[idx];
            __syncthreads();
            #pragma unroll
            for (int r = 0; r < 4; r++) {
                int idx = tid + r * 256;
                int t = idx >> 5, o = idx & 31;
                if (t >= s) {
                    float a = acc[r];
                    const float* ur = &u[(t - s) * DD];
                    #pragma unroll
                    for (int d = 0; d < DD; d++)
                        a += ur[d] * Fsh[d * OO + o];
                    acc[r] = a;
                }
            }
            __syncthreads();
        }
        #pragma unroll
        for (int r = 0; r < 4; r++) { int idx = tid + r * 256; delta[idx] = acc[r]; }
        __syncthreads();
        if (tid < OO) {
            int o = tid;
            y1[o] = 0.f; y2[o] = 0.f;
            __syncwarp();
            for (int t = 0; t < TFIX; t++) {
                float a = delta[t * OO + o];
                #pragma unroll
                for (int i = 0; i < OO; i++)
                    a += M1t[i * 32 + o] * y1[i] + M2t[i * 32 + o] * y2[i];
                __syncwarp();
                y2[o] = y1[o];
                __syncwarp();
                y1[o] = a;
                __syncwarp();
                out[((size_t)(b * LSEQ + t)) * OO + o] = a;
            }
        }
    }
}

// ---------------- launch 5: inverse FFT (radix-16, 256 thr) ------------------
__global__ void k_ifft(float* __restrict__ out) {
    __shared__ __align__(16) float2 sh[FFT_SH];
    int blk = blockIdx.x;                   // 512: (b, opair)
    int b = blk >> 4, op = blk & 15;
    int tid = threadIdx.x;                  // 256
    #pragma unroll
    for (int rr = 0; rr < 8; rr++) {
        int f = tid + rr * 256;             // 0..2047
        float2 a = __half22float2(g_Gh[b][2 * op][f]);
        float2 c = __half22float2(g_Gh[b][2 * op + 1][f]);
        sh[PHYS(f)] = make_float2(a.x - c.y, a.y + c.x);
        if (f > 0)
            sh[PHYS(NFFT - f)] = make_float2(a.x + c.y, c.x - a.y);
    }
    if (tid == 0) {
        float2 a = __half22float2(g_Gh[b][2 * op][2048]);
        float2 c = __half22float2(g_Gh[b][2 * op + 1][2048]);
        sh[PHYS(2048)] = make_float2(a.x - c.y, a.y + c.x);
    }
    fft16(sh, 1);
    const float inv = 1.f / (float)NFFT;
    for (int t = tid; t < LSEQ; t += 256) {
        if (t < TFIX) continue;             // fix (launch 4) owns these
        float2 z = sh[PHYS(t)];
        float2* p = reinterpret_cast<float2*>(out + ((size_t)(b * LSEQ + t)) * OO + 2 * op);
        *p = make_float2(z.x * inv, z.y * inv);
    }
}

// ---------------- launch ------------------------------------------------------
extern "C" void kernel_launch(void* const* d_in, const int* in_sizes, int n_in,
                              void* d_out, int out_size) {
    const float* inputs  = (const float*)d_in[0];
    const float* eigvals = (const float*)d_in[1];
    const float* eigvecs = (const float*)d_in[2];
    const float* m_u     = (const float*)d_in[3];
    const float* m_phi   = (const float*)d_in[4];
    const float* m_y     = (const float*)d_in[5];
    float* out = (float*)d_out;

    k_pre    <<<53, 1024>>>(m_y, eigvals, eigvecs, m_phi);      // launch 1
    k_fwd    <<<512, 256>>>(inputs);                            // launch 2
    k_W      <<<FH / 2, 1024>>>(eigvals, m_phi, m_u);           // launch 3
    k_mulfix <<<BB + FH / 4, 256>>>(inputs, m_u, m_y, out);     // launch 4 (profiled)
    k_ifft   <<<BB * OO / 2, 256>>>(out);                       // launch 5
}

// round 15
// speedup vs baseline: 1.3041x; 1.2327x over previous
#include <cuda_runtime.h>
#include <cuda_fp16.h>
#include <math.h>

#define NFFT  4096
#define LOGN  12
#define LSEQ  2048
#define BB    32
#define DD    32
#define KK    32
#define OO    32
#define JH    24      // truncated impulse-response length of y-recurrence
#define FH    2064    // padded half-spectrum bin count (>= 2049)
#define TFIX  32      // first TFIX timesteps recomputed exactly (alias reaches t<=22)

// padded shared-FFT addressing
#define PHYS(i) ((i) + ((i) >> 2))
#define FFT_SH  (NFFT + NFFT / 4)   // 5120 float2 = 40 KB

// ---------------- scratch (device globals; no allocation allowed) ------------
__device__ __half2 g_Uh[BB][DD][FH];   // FFT of inputs (fp16)   (b, d, f<=half)
__device__ __half2 g_Gh[BB][OO][FH];   // output spectra (fp16)  (b, o, f<=half)
__device__ __half2 g_Wh[FH][DD][OO];   // combined filter (fp16) (f<=half, d, o)
__device__ float2  g_V[KK][FH];        // FFT of eig_vecs        (k, f<=half)
__device__ float   g_h[JH][OO][OO];    // impulse response of recurrence
__device__ float   g_Fs[TFIX][DD][OO]; // time-domain F for the fixup region
__device__ float2  g_tw[NFFT];         // twiddles, per-stage layout [half + p]

// ---------------- helpers ----------------------------------------------------
__device__ __forceinline__ float2 cmulf(float2 a, float2 b) {
    return make_float2(a.x*b.x - a.y*b.y, a.x*b.y + a.y*b.x);
}

__device__ __forceinline__ void bfly4(float2& A, float2& B, float2& C, float2& D,
                                      int inverse) {
    float2 t0 = make_float2(A.x + C.x, A.y + C.y);
    float2 t1 = make_float2(A.x - C.x, A.y - C.y);
    float2 t2 = make_float2(B.x + D.x, B.y + D.y);
    float2 t3 = make_float2(B.x - D.x, B.y - D.y);
    A = make_float2(t0.x + t2.x, t0.y + t2.y);
    C = make_float2(t0.x - t2.x, t0.y - t2.y);
    if (!inverse) {
        B = make_float2(t1.x + t3.y, t1.y - t3.x);
        D = make_float2(t1.x - t3.y, t1.y + t3.x);
    } else {
        B = make_float2(t1.x - t3.y, t1.y + t3.x);
        D = make_float2(t1.x + t3.y, t1.y - t3.x);
    }
}

// Radix-16 FFT over 4096 complex values in PADDED shared memory (element i at
// x[PHYS(i)], natural order). 256 threads; 16 elements/thread; 3 shared rounds.
// The __syncthreads() between gather and scatter in pair 0 is load-bearing.
__device__ void fft16(float2* x, int inverse) {
    int tid = threadIdx.x;   // 256
    __syncthreads();
    // ---- pair 0: stages q=1 and q=4; reads digit-reversed, writes 16t+j ----
    {
        int revT = ((tid & 3) << 6) | (((tid >> 2) & 3) << 4)
                 | (((tid >> 4) & 3) << 2) | ((tid >> 6) & 3);
        float2 v[16];
        #pragma unroll
        for (int j = 0; j < 16; j++) {
            int src = revT + ((j >> 2) << 8) + ((j & 3) << 10);
            v[j] = x[PHYS(src)];
        }
        __syncthreads();   // all gathers complete before any scatter
        #pragma unroll
        for (int c = 0; c < 4; c++)
            bfly4(v[4*c], v[4*c+1], v[4*c+2], v[4*c+3], inverse);
        #pragma unroll
        for (int c = 0; c < 4; c++) {
            float2 w1 = __ldg(&g_tw[8 + c]);
            float2 w2 = __ldg(&g_tw[4 + c]);
            if (inverse) { w1.y = -w1.y; w2.y = -w2.y; }
            float2 w3 = cmulf(w1, w2);
            v[c+4]  = cmulf(v[c+4],  w1);
            v[c+8]  = cmulf(v[c+8],  w2);
            v[c+12] = cmulf(v[c+12], w3);
            bfly4(v[c], v[c+4], v[c+8], v[c+12], inverse);
        }
        int base = tid << 4;
        #pragma unroll
        for (int j = 0; j < 16; j++) x[PHYS(base + j)] = v[j];
    }
    __syncthreads();
    // ---- pair 1: stages q=16 and q=64 ----------------------------------------
    {
        int p = tid & 15;
        int base = ((tid >> 4) << 8) | p;
        float2 v[16];
        #pragma unroll
        for (int j = 0; j < 16; j++) v[j] = x[PHYS(base + j * 16)];
        float2 w1 = __ldg(&g_tw[32 + p]);
        float2 w2 = __ldg(&g_tw[16 + p]);
        if (inverse) { w1.y = -w1.y; w2.y = -w2.y; }
        float2 w3 = cmulf(w1, w2);
        #pragma unroll
        for (int c = 0; c < 4; c++) {
            v[4*c+1] = cmulf(v[4*c+1], w1);
            v[4*c+2] = cmulf(v[4*c+2], w2);
            v[4*c+3] = cmulf(v[4*c+3], w3);
            bfly4(v[4*c], v[4*c+1], v[4*c+2], v[4*c+3], inverse);
        }
        #pragma unroll
        for (int c = 0; c < 4; c++) {
            int pc = p + c * 16;
            float2 u1 = __ldg(&g_tw[128 + pc]);
            float2 u2 = __ldg(&g_tw[64 + pc]);
            if (inverse) { u1.y = -u1.y; u2.y = -u2.y; }
            float2 u3 = cmulf(u1, u2);
            v[c+4]  = cmulf(v[c+4],  u1);
            v[c+8]  = cmulf(v[c+8],  u2);
            v[c+12] = cmulf(v[c+12], u3);
            bfly4(v[c], v[c+4], v[c+8], v[c+12], inverse);
        }
        #pragma unroll
        for (int j = 0; j < 16; j++) x[PHYS(base + j * 16)] = v[j];
    }
    __syncthreads();
    // ---- pair 2: stages q=256 and q=1024 -------------------------------------
    {
        int p = tid;
        float2 v[16];
        #pragma unroll
        for (int j = 0; j < 16; j++) v[j] = x[PHYS(p + j * 256)];
        float2 w1 = __ldg(&g_tw[512 + p]);
        float2 w2 = __ldg(&g_tw[256 + p]);
        if (inverse) { w1.y = -w1.y; w2.y = -w2.y; }
        float2 w3 = cmulf(w1, w2);
        #pragma unroll
        for (int c = 0; c < 4; c++) {
            v[4*c+1] = cmulf(v[4*c+1], w1);
            v[4*c+2] = cmulf(v[4*c+2], w2);
            v[4*c+3] = cmulf(v[4*c+3], w3);
            bfly4(v[4*c], v[4*c+1], v[4*c+2], v[4*c+3], inverse);
        }
        #pragma unroll
        for (int c = 0; c < 4; c++) {
            int pc = p + c * 256;
            float2 u1 = __ldg(&g_tw[2048 + pc]);
            float2 u2 = __ldg(&g_tw[1024 + pc]);
            if (inverse) { u1.y = -u1.y; u2.y = -u2.y; }
            float2 u3 = cmulf(u1, u2);
            v[c+4]  = cmulf(v[c+4],  u1);
            v[c+8]  = cmulf(v[c+8],  u2);
            v[c+12] = cmulf(v[c+12], u3);
            bfly4(v[c], v[c+4], v[c+8], v[c+12], inverse);
        }
        #pragma unroll
        for (int j = 0; j < 16; j++) x[PHYS(p + j * 256)] = v[j];
    }
    __syncthreads();
}

// Forward FFT with PRIVATE sincos twiddles — eig-vec FFT blocks inside k_pre.
__device__ void fft_shared_sc(float2* x) {
    int tid = threadIdx.x;                  // 1024
    __syncthreads();
    #pragma unroll
    for (int k = 0; k < 4; k++) {
        int i = (tid & 3) | (((tid >> 2) & 3) << 8) | (((tid >> 4) & 63) << 2) | (k << 10);
        unsigned r = __brev((unsigned)i) >> 20;
        r = ((r & 0x555u) << 1) | ((r >> 1) & 0x555u);
        if ((unsigned)i < r) {
            float2 t = x[PHYS(i)];
            x[PHYS(i)] = x[PHYS((int)r)];
            x[PHYS((int)r)] = t;
        }
    }
    __syncthreads();
    {
        float2* xp = x + 5 * tid;
        float2 A = xp[0], B = xp[1], C = xp[2], D = xp[3];
        bfly4(A, B, C, D, 0);
        xp[0] = A; xp[1] = B; xp[2] = C; xp[3] = D;
    }
    __syncthreads();
    for (int s = 1; s < 6; s++) {
        int q = 1 << (2 * s);
        int stq = q + (q >> 2);
        int p = tid & (q - 1);
        int g = tid >> (2 * s);
        int pb = PHYS((g << (2 * s + 2)) + p);
        float s1, c1, s2, c2;
        sincosf(-3.14159265358979323846f * (float)p / (float)(2 * q), &s1, &c1);
        sincosf(-3.14159265358979323846f * (float)p / (float)q, &s2, &c2);
        float2 w1 = make_float2(c1, s1);
        float2 w2 = make_float2(c2, s2);
        float2 w3 = cmulf(w1, w2);
        float2 A = x[pb];
        float2 B = cmulf(x[pb + stq], w1);
        float2 C = cmulf(x[pb + 2 * stq], w2);
        float2 D = cmulf(x[pb + 3 * stq], w3);
        bfly4(A, B, C, D, 0);
        x[pb] = A; x[pb + stq] = B; x[pb + 2 * stq] = C; x[pb + 3 * stq] = D;
        __syncthreads();
    }
}

// ---------------- launch 1: twiddles + h + eig-vec FFTs + Fs -----------------
__global__ void k_pre(const float* __restrict__ m_y,
                      const float* __restrict__ eig_vals,
                      const float* __restrict__ ev,
                      const float* __restrict__ m_phi) {
    __shared__ __align__(16) char raw[FFT_SH * 8];   // 40 KB, reused per role
    int blk = blockIdx.x;
    int tid = threadIdx.x;                  // 1024
    if (blk < 4) {
        int i = blk * 1024 + tid;
        if (i == 0) { g_tw[0] = make_float2(1.f, 0.f); return; }
        int s = 31 - __clz(i);
        int half = 1 << s;
        int p = i - half;
        float ang = -3.14159265358979323846f * (float)p / (float)half;
        float sn, cs; sincosf(ang, &sn, &cs);
        g_tw[i] = make_float2(cs, sn);
    } else if (blk == 4) {
        float* M1  = reinterpret_cast<float*>(raw);
        float* M2  = M1 + OO * OO;
        float* hp  = M2 + OO * OO;
        float* hp2 = hp + OO * OO;
        int o = tid >> 5, i = tid & 31;
        M1[o * 32 + i] = m_y[o * 64 + i];
        M2[o * 32 + i] = m_y[o * 64 + 32 + i];
        float h0 = (o == i) ? 1.f : 0.f;
        hp2[o * 32 + i] = h0;
        g_h[0][o][i] = h0;
        hp[o * 32 + i] = m_y[o * 64 + i];
        g_h[1][o][i] = m_y[o * 64 + i];
        __syncthreads();
        for (int j = 2; j < JH; j++) {
            float acc = 0.f;
            #pragma unroll
            for (int t = 0; t < 32; t++)
                acc += M1[o * 32 + t] * hp[t * 32 + i] + M2[o * 32 + t] * hp2[t * 32 + i];
            __syncthreads();
            hp2[o * 32 + i] = hp[o * 32 + i];
            __syncthreads();
            hp[o * 32 + i] = acc;
            g_h[j][o][i] = acc;
            __syncthreads();
        }
    } else if (blk < 21) {
        float2* sh = reinterpret_cast<float2*>(raw);
        int kp = blk - 5;                   // 0..15 -> filters 2kp, 2kp+1
        for (int t = tid; t < LSEQ; t += 1024) {
            const float2 v = *reinterpret_cast<const float2*>(ev + (size_t)t * KK + 2 * kp);
            sh[PHYS(t)] = v;
        }
        for (int t = LSEQ + tid; t < NFFT; t += 1024) sh[PHYS(t)] = make_float2(0.f, 0.f);
        fft_shared_sc(sh);
        for (int f = tid; f < FH; f += 1024) {
            float2 zf = sh[PHYS(f)];
            int m = (NFFT - f) & (NFFT - 1);
            float2 zm = sh[PHYS(m)];
            g_V[2 * kp][f]     = make_float2(0.5f * (zf.x + zm.x), 0.5f * (zf.y - zm.y));
            g_V[2 * kp + 1][f] = make_float2(0.5f * (zf.y + zm.y), 0.5f * (zm.x - zf.x));
        }
    } else {
        float* sc = reinterpret_cast<float*>(raw);
        float* vv = sc + KK;
        int s = blk - 21;                   // 0..TFIX-1
        if (tid < KK) {
            sc[tid] = sqrtf(sqrtf(eig_vals[tid]));
            vv[tid] = ev[(size_t)s * KK + tid];
        }
        __syncthreads();
        int d = tid >> 5, o = tid & 31;
        float acc = 0.f;
        #pragma unroll
        for (int k = 0; k < KK; k++)
            acc += sc[k] * vv[k] * m_phi[(k * DD + d) * OO + o];
        g_Fs[s][d][o] = acc;
    }
}

// ---------------- launch 2: forward FFTs of inputs (radix-16, 256 thr) -------
__global__ void k_fwd(const float* __restrict__ inp) {
    __shared__ __align__(16) float2 sh[FFT_SH];
    int blk = blockIdx.x;                   // 512: (b, dpair)
    int b = blk >> 4, dp = blk & 15;
    int tid = threadIdx.x;                  // 256
    #pragma unroll
    for (int rr = 0; rr < 8; rr++) {
        int t = tid + rr * 256;
        const float2 v = *reinterpret_cast<const float2*>(
            inp + ((size_t)(b * LSEQ + t)) * DD + 2 * dp);
        sh[PHYS(t)] = v;
    }
    #pragma unroll
    for (int rr = 0; rr < 8; rr++) {
        int t = LSEQ + tid + rr * 256;
        sh[PHYS(t)] = make_float2(0.f, 0.f);
    }
    fft16(sh, 0);
    for (int f = tid; f < FH; f += 256) {
        float2 zf = sh[PHYS(f)];
        int m = (NFFT - f) & (NFFT - 1);
        float2 zm = sh[PHYS(m)];
        g_Uh[b][2 * dp][f]     = __floats2half2_rn(0.5f * (zf.x + zm.x), 0.5f * (zf.y - zm.y));
        g_Uh[b][2 * dp + 1][f] = __floats2half2_rn(0.5f * (zf.y + zm.y), 0.5f * (zm.x - zf.x));
    }
}

// ---------------- launch 3: fused combined filter W (2 bins / block) ---------
__global__ void k_W(const float* __restrict__ eig_vals,
                    const float* __restrict__ m_phi,
                    const float* __restrict__ m_u) {
    __shared__ float2 Hs[2][OO][OO + 1];    // transposed: Hs[bin][o'][o]
    __shared__ float2 FAs[2][DD][OO];
    __shared__ float2 sv[2][KK];
    __shared__ float2 wpre[2][JH];          // e^{-i 2pi f j / N}
    int f0 = blockIdx.x * 2;
    int tid = threadIdx.x;                  // 1024
    int o = tid >> 5, i = tid & 31;

    if (tid < 2 * JH) {
        int bin = tid >= JH ? 1 : 0;
        int j = tid - bin * JH;
        float ang = -6.283185307179586f * (float)(f0 + bin) * (float)j / (float)NFFT;
        float sn, cs; sincosf(ang, &sn, &cs);
        wpre[bin][j] = make_float2(cs, sn);
    }
    if (tid >= 64 && tid < 128) {
        int bin = (tid - 64) >> 5, k = tid & 31;
        float sc = sqrtf(sqrtf(eig_vals[k]));
        float2 v = g_V[k][f0 + bin];
        sv[bin][k] = make_float2(v.x * sc, v.y * sc);
    }
    __syncthreads();

    float2 acc0 = make_float2(0.f, 0.f), acc1 = acc0;
    #pragma unroll 4
    for (int j = 0; j < JH; j++) {
        float hv = g_h[j][o][i];
        float2 w0j = wpre[0][j];
        float2 w1j = wpre[1][j];
        acc0.x += hv * w0j.x; acc0.y += hv * w0j.y;
        acc1.x += hv * w1j.x; acc1.y += hv * w1j.y;
    }
    Hs[0][i][o] = acc0;
    Hs[1][i][o] = acc1;

    int d = o, q = i;
    float2 fa0 = make_float2(0.f, 0.f), fa1 = fa0;
    #pragma unroll 8
    for (int k = 0; k < KK; k++) {
        float m = m_phi[(k * DD + d) * OO + q];
        fa0.x += sv[0][k].x * m; fa0.y += sv[0][k].y * m;
        fa1.x += sv[1][k].x * m; fa1.y += sv[1][k].y * m;
    }
    float a0 = m_u[(q * DD + d) * 3 + 0];
    float a1 = m_u[(q * DD + d) * 3 + 1];
    float a2 = m_u[(q * DD + d) * 3 + 2];
    {
        float2 e1 = wpre[0][1], e2 = wpre[0][2];
        fa0.x += a0 + a1 * e1.x + a2 * e2.x;
        fa0.y += a1 * e1.y + a2 * e2.y;
    }
    {
        float2 e1 = wpre[1][1], e2 = wpre[1][2];
        fa1.x += a0 + a1 * e1.x + a2 * e2.x;
        fa1.y += a1 * e1.y + a2 * e2.y;
    }
    FAs[0][d][q] = fa0;
    FAs[1][d][q] = fa1;
    __syncthreads();

    float2 r0 = make_float2(0.f, 0.f), r1 = r0;
    #pragma unroll 8
    for (int t = 0; t < OO; t++) {
        float2 A = FAs[0][d][t];
        float2 h = Hs[0][t][i];
        r0.x += A.x * h.x - A.y * h.y;
        r0.y += A.x * h.y + A.y * h.x;
        float2 B = FAs[1][d][t];
        float2 g = Hs[1][t][i];
        r1.x += B.x * g.x - B.y * g.y;
        r1.y += B.x * g.y + B.y * g.x;
    }
    g_Wh[f0][d][i]     = __floats2half2_rn(r0.x, r0.y);
    g_Wh[f0 + 1][d][i] = __floats2half2_rn(r1.x, r1.y);
}

// ---------------- launch 4: fix (blocks 0..31) + k_mul (blocks 32..547) ------
__global__ void k_mulfix(const float* __restrict__ inp,
                         const float* __restrict__ m_u,
                         const float* __restrict__ m_y,
                         float* __restrict__ out) {
    __shared__ __align__(16) char raw[BB * 4 * (DD + 2) * 8];   // 34.8 KB union
    int blk = blockIdx.x;
    int tid = threadIdx.x;                  // 256
    if (blk >= BB) {
        float2 (*Us)[4][DD + 2] = reinterpret_cast<float2(*)[4][DD + 2]>(raw);
        int f0 = (blk - BB) * 4;
        #pragma unroll
        for (int k = 0; k < 4; k++) {
            int pair = tid + k * 256;
            int b = pair >> 5, d = pair & 31;
            uint4 rw = *reinterpret_cast<const uint4*>(&g_Uh[b][d][f0]);
            __half2 h0 = *reinterpret_cast<__half2*>(&rw.x);
            __half2 h1 = *reinterpret_cast<__half2*>(&rw.y);
            __half2 h2 = *reinterpret_cast<__half2*>(&rw.z);
            __half2 h3 = *reinterpret_cast<__half2*>(&rw.w);
            Us[b][0][d] = __half22float2(h0);
            Us[b][1][d] = __half22float2(h1);
            Us[b][2][d] = __half22float2(h2);
            Us[b][3][d] = __half22float2(h3);
        }
        int bh = tid >> 7;
        int o  = (tid >> 2) & 31;
        int fi = tid & 3;
        int f  = f0 + fi;
        float2 Wreg[DD];
        #pragma unroll
        for (int d = 0; d < DD; d++) Wreg[d] = __half22float2(g_Wh[f][d][o]);
        __syncthreads();
        for (int bi = 0; bi < 16; bi++) {
            int b = bh * 16 + bi;
            float2 a0 = make_float2(0.f, 0.f), a1 = a0;
            const float4* up = reinterpret_cast<const float4*>(&Us[b][fi][0]);
            #pragma unroll
            for (int d2 = 0; d2 < DD / 2; d2++) {
                float4 uv = up[d2];
                float2 w0 = Wreg[2 * d2], w1 = Wreg[2 * d2 + 1];
                a0.x += uv.x * w0.x - uv.y * w0.y;
                a0.y += uv.x * w0.y + uv.y * w0.x;
                a1.x += uv.z * w1.x - uv.w * w1.y;
                a1.y += uv.z * w1.y + uv.w * w1.x;
            }
            g_Gh[b][o][f] = __floats2half2_rn(a0.x + a1.x, a0.y + a1.y);
        }
    } else {
        // ---- fix role: m_u staged TRANSPOSED in shared (coalesced reads,
        //      conflict-free lane-contiguous LDS) — kills the 32-way
        //      uncoalesced m_u LDGs that made this block take ~110us.
        float* u     = reinterpret_cast<float*>(raw);            // 1024 f
        float* Fsh   = u + TFIX * DD;                            // 1024 f
        float* delta = Fsh + DD * OO;                            // 1024 f
        float* M1t   = delta + TFIX * OO;                        // 1024 f
        float* M2t   = M1t + OO * OO;                            // 1024 f
        float* mu    = M2t + OO * OO;                            // 3072 f: mu[j*1024 + i*32 + o]
        float* y1    = mu + 3 * DD * OO;                         // 32 f
        float* y2    = y1 + OO;                                  // 32 f  (total 33.3 KB)
        int b = blk;
        for (int idx = tid; idx < TFIX * DD; idx += 256)
            u[idx] = inp[(size_t)b * LSEQ * DD + idx];
        for (int idx = tid; idx < OO * OO; idx += 256) {
            int i = idx >> 5, o = idx & 31;
            M1t[i * 32 + o] = m_y[o * 64 + i];
            M2t[i * 32 + o] = m_y[o * 64 + 32 + i];
        }
        for (int idx = tid; idx < 3 * DD * OO; idx += 256) {
            // m_u layout: m_u[(o*DD + i)*3 + j]; read coalesced, scatter transposed
            int j = idx % 3;
            int rem = idx / 3;          // o*32 + i
            int i = rem & 31;
            int o = rem >> 5;
            mu[j * (DD * OO) + i * 32 + o] = m_u[idx];
        }
        __syncthreads();
        float acc[4];
        #pragma unroll
        for (int r = 0; r < 4; r++) {
            int idx = tid + r * 256;
            int t = idx >> 5, o = idx & 31;
            float a = 0.f;
            #pragma unroll
            for (int j = 0; j < 3; j++) {
                if (t >= j) {
                    const float* mj = &mu[j * (DD * OO)];
                    const float* ur = &u[(t - j) * DD];
                    #pragma unroll
                    for (int i = 0; i < DD; i++)
                        a += mj[i * 32 + o] * ur[i];
                }
            }
            acc[r] = a;
        }
        for (int s = 0; s < TFIX; s++) {
            const float* fp = &g_Fs[s][0][0];
            for (int idx = tid; idx < DD * OO; idx += 256) Fsh[idx] = fp[idx];
            __syncthreads();
            #pragma unroll
            for (int r = 0; r < 4; r++) {
                int idx = tid + r * 256;
                int t = idx >> 5, o = idx & 31;
                if (t >= s) {
                    float a = acc[r];
                    const float* ur = &u[(t - s) * DD];
                    #pragma unroll
                    for (int d = 0; d < DD; d++)
                        a += ur[d] * Fsh[d * OO + o];
                    acc[r] = a;
                }
            }
            __syncthreads();
        }
        #pragma unroll
        for (int r = 0; r < 4; r++) { int idx = tid + r * 256; delta[idx] = acc[r]; }
        __syncthreads();
        if (tid < OO) {
            int o = tid;
            y1[o] = 0.f; y2[o] = 0.f;
            __syncwarp();
            for (int t = 0; t < TFIX; t++) {
                float a = delta[t * OO + o];
                #pragma unroll
                for (int i = 0; i < OO; i++)
                    a += M1t[i * 32 + o] * y1[i] + M2t[i * 32 + o] * y2[i];
                __syncwarp();
                y2[o] = y1[o];
                __syncwarp();
                y1[o] = a;
                __syncwarp();
                out[((size_t)(b * LSEQ + t)) * OO + o] = a;
            }
        }
    }
}

// ---------------- launch 5: inverse FFT (radix-16, 256 thr) ------------------
__global__ void k_ifft(float* __restrict__ out) {
    __shared__ __align__(16) float2 sh[FFT_SH];
    int blk = blockIdx.x;                   // 512: (b, opair)
    int b = blk >> 4, op = blk & 15;
    int tid = threadIdx.x;                  // 256
    #pragma unroll
    for (int rr = 0; rr < 8; rr++) {
        int f = tid + rr * 256;             // 0..2047
        float2 a = __half22float2(g_Gh[b][2 * op][f]);
        float2 c = __half22float2(g_Gh[b][2 * op + 1][f]);
        sh[PHYS(f)] = make_float2(a.x - c.y, a.y + c.x);
        if (f > 0)
            sh[PHYS(NFFT - f)] = make_float2(a.x + c.y, c.x - a.y);
    }
    if (tid == 0) {
        float2 a = __half22float2(g_Gh[b][2 * op][2048]);
        float2 c = __half22float2(g_Gh[b][2 * op + 1][2048]);
        sh[PHYS(2048)] = make_float2(a.x - c.y, a.y + c.x);
    }
    fft16(sh, 1);
    const float inv = 1.f / (float)NFFT;
    for (int t = tid; t < LSEQ; t += 256) {
        if (t < TFIX) continue;             // fix (launch 4) owns these
        float2 z = sh[PHYS(t)];
        float2* p = reinterpret_cast<float2*>(out + ((size_t)(b * LSEQ + t)) * OO + 2 * op);
        *p = make_float2(z.x * inv, z.y * inv);
    }
}

// ---------------- launch ------------------------------------------------------
extern "C" void kernel_launch(void* const* d_in, const int* in_sizes, int n_in,
                              void* d_out, int out_size) {
    const float* inputs  = (const float*)d_in[0];
    const float* eigvals = (const float*)d_in[1];
    const float* eigvecs = (const float*)d_in[2];
    const float* m_u     = (const float*)d_in[3];
    const float* m_phi   = (const float*)d_in[4];
    const float* m_y     = (const float*)d_in[5];
    float* out = (float*)d_out;

    k_pre    <<<53, 1024>>>(m_y, eigvals, eigvecs, m_phi);      // launch 1
    k_fwd    <<<512, 256>>>(inputs);                            // launch 2
    k_W      <<<FH / 2, 1024>>>(eigvals, m_phi, m_u);           // launch 3
    k_mulfix <<<BB + FH / 4, 256>>>(inputs, m_u, m_y, out);     // launch 4 (profiled)
    k_ifft   <<<BB * OO / 2, 256>>>(out);                       // launch 5
}

// round 16
// speedup vs baseline: 1.3576x; 1.0410x over previous
#include <cuda_runtime.h>
#include <cuda_fp16.h>
#include <math.h>

#define NFFT  4096
#define LOGN  12
#define LSEQ  2048
#define BB    32
#define DD    32
#define KK    32
#define OO    32
#define JH    24      // truncated impulse-response length of y-recurrence
#define FH    2064    // padded half-spectrum bin count (>= 2049)
#define TFIX  32      // first TFIX timesteps recomputed exactly (alias reaches t<=22)

// padded shared-FFT addressing
#define PHYS(i) ((i) + ((i) >> 2))
#define FFT_SH  (NFFT + NFFT / 4)   // 5120 float2 = 40 KB

// ---------------- scratch (device globals; no allocation allowed) ------------
__device__ __half2 g_Uh[BB][DD][FH];   // FFT of inputs (fp16)   (b, d, f<=half)
__device__ __half2 g_Gh[BB][OO][FH];   // output spectra (fp16)  (b, o, f<=half)
__device__ __half2 g_Wh[FH][DD][OO];   // combined filter (fp16) (f<=half, d, o)
__device__ float2  g_V[KK][FH];        // FFT of eig_vecs        (k, f<=half)
__device__ float   g_h[JH][OO][OO];    // impulse response of recurrence
__device__ float   g_Fs[TFIX][DD][OO]; // time-domain F for the fixup region
__device__ float2  g_tw[NFFT];         // twiddles, per-stage layout [half + p]

// ---------------- helpers ----------------------------------------------------
__device__ __forceinline__ float2 cmulf(float2 a, float2 b) {
    return make_float2(a.x*b.x - a.y*b.y, a.x*b.y + a.y*b.x);
}

__device__ __forceinline__ void bfly4(float2& A, float2& B, float2& C, float2& D,
                                      int inverse) {
    float2 t0 = make_float2(A.x + C.x, A.y + C.y);
    float2 t1 = make_float2(A.x - C.x, A.y - C.y);
    float2 t2 = make_float2(B.x + D.x, B.y + D.y);
    float2 t3 = make_float2(B.x - D.x, B.y - D.y);
    A = make_float2(t0.x + t2.x, t0.y + t2.y);
    C = make_float2(t0.x - t2.x, t0.y - t2.y);
    if (!inverse) {
        B = make_float2(t1.x + t3.y, t1.y - t3.x);
        D = make_float2(t1.x - t3.y, t1.y + t3.x);
    } else {
        B = make_float2(t1.x - t3.y, t1.y + t3.x);
        D = make_float2(t1.x + t3.y, t1.y - t3.x);
    }
}

// Radix-16 FFT over 4096 complex values in PADDED shared memory (element i at
// x[PHYS(i)], natural order). 256 threads; 16 elements/thread; 3 shared rounds.
// The __syncthreads() between gather and scatter in pair 0 is load-bearing.
__device__ void fft16(float2* x, int inverse) {
    int tid = threadIdx.x;   // 256
    __syncthreads();
    // ---- pair 0: stages q=1 and q=4; reads digit-reversed, writes 16t+j ----
    {
        int revT = ((tid & 3) << 6) | (((tid >> 2) & 3) << 4)
                 | (((tid >> 4) & 3) << 2) | ((tid >> 6) & 3);
        float2 v[16];
        #pragma unroll
        for (int j = 0; j < 16; j++) {
            int src = revT + ((j >> 2) << 8) + ((j & 3) << 10);
            v[j] = x[PHYS(src)];
        }
        __syncthreads();   // all gathers complete before any scatter
        #pragma unroll
        for (int c = 0; c < 4; c++)
            bfly4(v[4*c], v[4*c+1], v[4*c+2], v[4*c+3], inverse);
        #pragma unroll
        for (int c = 0; c < 4; c++) {
            float2 w1 = __ldg(&g_tw[8 + c]);
            float2 w2 = __ldg(&g_tw[4 + c]);
            if (inverse) { w1.y = -w1.y; w2.y = -w2.y; }
            float2 w3 = cmulf(w1, w2);
            v[c+4]  = cmulf(v[c+4],  w1);
            v[c+8]  = cmulf(v[c+8],  w2);
            v[c+12] = cmulf(v[c+12], w3);
            bfly4(v[c], v[c+4], v[c+8], v[c+12], inverse);
        }
        int base = tid << 4;
        #pragma unroll
        for (int j = 0; j < 16; j++) x[PHYS(base + j)] = v[j];
    }
    __syncthreads();
    // ---- pair 1: stages q=16 and q=64 ----------------------------------------
    {
        int p = tid & 15;
        int base = ((tid >> 4) << 8) | p;
        float2 v[16];
        #pragma unroll
        for (int j = 0; j < 16; j++) v[j] = x[PHYS(base + j * 16)];
        float2 w1 = __ldg(&g_tw[32 + p]);
        float2 w2 = __ldg(&g_tw[16 + p]);
        if (inverse) { w1.y = -w1.y; w2.y = -w2.y; }
        float2 w3 = cmulf(w1, w2);
        #pragma unroll
        for (int c = 0; c < 4; c++) {
            v[4*c+1] = cmulf(v[4*c+1], w1);
            v[4*c+2] = cmulf(v[4*c+2], w2);
            v[4*c+3] = cmulf(v[4*c+3], w3);
            bfly4(v[4*c], v[4*c+1], v[4*c+2], v[4*c+3], inverse);
        }
        #pragma unroll
        for (int c = 0; c < 4; c++) {
            int pc = p + c * 16;
            float2 u1 = __ldg(&g_tw[128 + pc]);
            float2 u2 = __ldg(&g_tw[64 + pc]);
            if (inverse) { u1.y = -u1.y; u2.y = -u2.y; }
            float2 u3 = cmulf(u1, u2);
            v[c+4]  = cmulf(v[c+4],  u1);
            v[c+8]  = cmulf(v[c+8],  u2);
            v[c+12] = cmulf(v[c+12], u3);
            bfly4(v[c], v[c+4], v[c+8], v[c+12], inverse);
        }
        #pragma unroll
        for (int j = 0; j < 16; j++) x[PHYS(base + j * 16)] = v[j];
    }
    __syncthreads();
    // ---- pair 2: stages q=256 and q=1024 -------------------------------------
    {
        int p = tid;
        float2 v[16];
        #pragma unroll
        for (int j = 0; j < 16; j++) v[j] = x[PHYS(p + j * 256)];
        float2 w1 = __ldg(&g_tw[512 + p]);
        float2 w2 = __ldg(&g_tw[256 + p]);
        if (inverse) { w1.y = -w1.y; w2.y = -w2.y; }
        float2 w3 = cmulf(w1, w2);
        #pragma unroll
        for (int c = 0; c < 4; c++) {
            v[4*c+1] = cmulf(v[4*c+1], w1);
            v[4*c+2] = cmulf(v[4*c+2], w2);
            v[4*c+3] = cmulf(v[4*c+3], w3);
            bfly4(v[4*c], v[4*c+1], v[4*c+2], v[4*c+3], inverse);
        }
        #pragma unroll
        for (int c = 0; c < 4; c++) {
            int pc = p + c * 256;
            float2 u1 = __ldg(&g_tw[2048 + pc]);
            float2 u2 = __ldg(&g_tw[1024 + pc]);
            if (inverse) { u1.y = -u1.y; u2.y = -u2.y; }
            float2 u3 = cmulf(u1, u2);
            v[c+4]  = cmulf(v[c+4],  u1);
            v[c+8]  = cmulf(v[c+8],  u2);
            v[c+12] = cmulf(v[c+12], u3);
            bfly4(v[c], v[c+4], v[c+8], v[c+12], inverse);
        }
        #pragma unroll
        for (int j = 0; j < 16; j++) x[PHYS(p + j * 256)] = v[j];
    }
    __syncthreads();
}

// Forward FFT with PRIVATE sincos twiddles — eig-vec FFT blocks inside k_pre.
__device__ void fft_shared_sc(float2* x) {
    int tid = threadIdx.x;                  // 1024
    __syncthreads();
    #pragma unroll
    for (int k = 0; k < 4; k++) {
        int i = (tid & 3) | (((tid >> 2) & 3) << 8) | (((tid >> 4) & 63) << 2) | (k << 10);
        unsigned r = __brev((unsigned)i) >> 20;
        r = ((r & 0x555u) << 1) | ((r >> 1) & 0x555u);
        if ((unsigned)i < r) {
            float2 t = x[PHYS(i)];
            x[PHYS(i)] = x[PHYS((int)r)];
            x[PHYS((int)r)] = t;
        }
    }
    __syncthreads();
    {
        float2* xp = x + 5 * tid;
        float2 A = xp[0], B = xp[1], C = xp[2], D = xp[3];
        bfly4(A, B, C, D, 0);
        xp[0] = A; xp[1] = B; xp[2] = C; xp[3] = D;
    }
    __syncthreads();
    for (int s = 1; s < 6; s++) {
        int q = 1 << (2 * s);
        int stq = q + (q >> 2);
        int p = tid & (q - 1);
        int g = tid >> (2 * s);
        int pb = PHYS((g << (2 * s + 2)) + p);
        float s1, c1, s2, c2;
        sincosf(-3.14159265358979323846f * (float)p / (float)(2 * q), &s1, &c1);
        sincosf(-3.14159265358979323846f * (float)p / (float)q, &s2, &c2);
        float2 w1 = make_float2(c1, s1);
        float2 w2 = make_float2(c2, s2);
        float2 w3 = cmulf(w1, w2);
        float2 A = x[pb];
        float2 B = cmulf(x[pb + stq], w1);
        float2 C = cmulf(x[pb + 2 * stq], w2);
        float2 D = cmulf(x[pb + 3 * stq], w3);
        bfly4(A, B, C, D, 0);
        x[pb] = A; x[pb + stq] = B; x[pb + 2 * stq] = C; x[pb + 3 * stq] = D;
        __syncthreads();
    }
}

// ---------------- launch 1: twiddles + h + eig-vec FFTs + Fs -----------------
__global__ void k_pre(const float* __restrict__ m_y,
                      const float* __restrict__ eig_vals,
                      const float* __restrict__ ev,
                      const float* __restrict__ m_phi) {
    __shared__ __align__(16) char raw[FFT_SH * 8];   // 40 KB, reused per role
    int blk = blockIdx.x;
    int tid = threadIdx.x;                  // 1024
    if (blk < 4) {
        int i = blk * 1024 + tid;
        if (i == 0) { g_tw[0] = make_float2(1.f, 0.f); return; }
        int s = 31 - __clz(i);
        int half = 1 << s;
        int p = i - half;
        float ang = -3.14159265358979323846f * (float)p / (float)half;
        float sn, cs; sincosf(ang, &sn, &cs);
        g_tw[i] = make_float2(cs, sn);
    } else if (blk == 4) {
        float* M1  = reinterpret_cast<float*>(raw);
        float* M2  = M1 + OO * OO;
        float* hp  = M2 + OO * OO;
        float* hp2 = hp + OO * OO;
        int o = tid >> 5, i = tid & 31;
        M1[o * 32 + i] = m_y[o * 64 + i];
        M2[o * 32 + i] = m_y[o * 64 + 32 + i];
        float h0 = (o == i) ? 1.f : 0.f;
        hp2[o * 32 + i] = h0;
        g_h[0][o][i] = h0;
        hp[o * 32 + i] = m_y[o * 64 + i];
        g_h[1][o][i] = m_y[o * 64 + i];
        __syncthreads();
        for (int j = 2; j < JH; j++) {
            float acc = 0.f;
            #pragma unroll
            for (int t = 0; t < 32; t++)
                acc += M1[o * 32 + t] * hp[t * 32 + i] + M2[o * 32 + t] * hp2[t * 32 + i];
            __syncthreads();
            hp2[o * 32 + i] = hp[o * 32 + i];
            __syncthreads();
            hp[o * 32 + i] = acc;
            g_h[j][o][i] = acc;
            __syncthreads();
        }
    } else if (blk < 21) {
        float2* sh = reinterpret_cast<float2*>(raw);
        int kp = blk - 5;                   // 0..15 -> filters 2kp, 2kp+1
        for (int t = tid; t < LSEQ; t += 1024) {
            const float2 v = *reinterpret_cast<const float2*>(ev + (size_t)t * KK + 2 * kp);
            sh[PHYS(t)] = v;
        }
        for (int t = LSEQ + tid; t < NFFT; t += 1024) sh[PHYS(t)] = make_float2(0.f, 0.f);
        fft_shared_sc(sh);
        for (int f = tid; f < FH; f += 1024) {
            float2 zf = sh[PHYS(f)];
            int m = (NFFT - f) & (NFFT - 1);
            float2 zm = sh[PHYS(m)];
            g_V[2 * kp][f]     = make_float2(0.5f * (zf.x + zm.x), 0.5f * (zf.y - zm.y));
            g_V[2 * kp + 1][f] = make_float2(0.5f * (zf.y + zm.y), 0.5f * (zm.x - zf.x));
        }
    } else {
        float* sc = reinterpret_cast<float*>(raw);
        float* vv = sc + KK;
        int s = blk - 21;                   // 0..TFIX-1
        if (tid < KK) {
            sc[tid] = sqrtf(sqrtf(eig_vals[tid]));
            vv[tid] = ev[(size_t)s * KK + tid];
        }
        __syncthreads();
        int d = tid >> 5, o = tid & 31;
        float acc = 0.f;
        #pragma unroll
        for (int k = 0; k < KK; k++)
            acc += sc[k] * vv[k] * m_phi[(k * DD + d) * OO + o];
        g_Fs[s][d][o] = acc;
    }
}

// ---------------- launch 2: forward FFTs of inputs (radix-16, 256 thr) -------
__global__ void k_fwd(const float* __restrict__ inp) {
    __shared__ __align__(16) float2 sh[FFT_SH];
    int blk = blockIdx.x;                   // 512: (b, dpair)
    int b = blk >> 4, dp = blk & 15;
    int tid = threadIdx.x;                  // 256
    #pragma unroll
    for (int rr = 0; rr < 8; rr++) {
        int t = tid + rr * 256;
        const float2 v = *reinterpret_cast<const float2*>(
            inp + ((size_t)(b * LSEQ + t)) * DD + 2 * dp);
        sh[PHYS(t)] = v;
    }
    #pragma unroll
    for (int rr = 0; rr < 8; rr++) {
        int t = LSEQ + tid + rr * 256;
        sh[PHYS(t)] = make_float2(0.f, 0.f);
    }
    fft16(sh, 0);
    for (int f = tid; f < FH; f += 256) {
        float2 zf = sh[PHYS(f)];
        int m = (NFFT - f) & (NFFT - 1);
        float2 zm = sh[PHYS(m)];
        g_Uh[b][2 * dp][f]     = __floats2half2_rn(0.5f * (zf.x + zm.x), 0.5f * (zf.y - zm.y));
        g_Uh[b][2 * dp + 1][f] = __floats2half2_rn(0.5f * (zf.y + zm.y), 0.5f * (zm.x - zf.x));
    }
}

// ---------------- launch 3: combined filter W + exact fixup ------------------
// blocks 0..1031: k_W (2 bins/block); blocks 1032..1063: fix (batch b)
__global__ void k_Wfix(const float* __restrict__ eig_vals,
                       const float* __restrict__ m_phi,
                       const float* __restrict__ m_u,
                       const float* __restrict__ inp,
                       const float* __restrict__ m_y,
                       float* __restrict__ out) {
    __shared__ __align__(16) char raw[35840];   // 35 KB union
    int blk = blockIdx.x;
    int tid = threadIdx.x;                  // 1024
    if (blk < FH / 2) {
        // ---- k_W role (unchanged from R15) ----
        float2 (*Hs)[OO][OO + 1] = reinterpret_cast<float2(*)[OO][OO + 1]>(raw);       // 16896 B
        float2 (*FAs)[DD][OO]    = reinterpret_cast<float2(*)[DD][OO]>(raw + 16896);   // 16384 B
        float2 (*sv)[KK]         = reinterpret_cast<float2(*)[KK]>(raw + 33280);       // 512 B
        float2 (*wpre)[JH]       = reinterpret_cast<float2(*)[JH]>(raw + 33792);       // 384 B
        int f0 = blk * 2;
        int o = tid >> 5, i = tid & 31;

        if (tid < 2 * JH) {
            int bin = tid >= JH ? 1 : 0;
            int j = tid - bin * JH;
            float ang = -6.283185307179586f * (float)(f0 + bin) * (float)j / (float)NFFT;
            float sn, cs; sincosf(ang, &sn, &cs);
            wpre[bin][j] = make_float2(cs, sn);
        }
        if (tid >= 64 && tid < 128) {
            int bin = (tid - 64) >> 5, k = tid & 31;
            float sc = sqrtf(sqrtf(eig_vals[k]));
            float2 v = g_V[k][f0 + bin];
            sv[bin][k] = make_float2(v.x * sc, v.y * sc);
        }
        __syncthreads();

        float2 acc0 = make_float2(0.f, 0.f), acc1 = acc0;
        #pragma unroll 4
        for (int j = 0; j < JH; j++) {
            float hv = g_h[j][o][i];
            float2 w0j = wpre[0][j];
            float2 w1j = wpre[1][j];
            acc0.x += hv * w0j.x; acc0.y += hv * w0j.y;
            acc1.x += hv * w1j.x; acc1.y += hv * w1j.y;
        }
        Hs[0][i][o] = acc0;
        Hs[1][i][o] = acc1;

        int d = o, q = i;
        float2 fa0 = make_float2(0.f, 0.f), fa1 = fa0;
        #pragma unroll 8
        for (int k = 0; k < KK; k++) {
            float m = m_phi[(k * DD + d) * OO + q];
            fa0.x += sv[0][k].x * m; fa0.y += sv[0][k].y * m;
            fa1.x += sv[1][k].x * m; fa1.y += sv[1][k].y * m;
        }
        float a0 = m_u[(q * DD + d) * 3 + 0];
        float a1 = m_u[(q * DD + d) * 3 + 1];
        float a2 = m_u[(q * DD + d) * 3 + 2];
        {
            float2 e1 = wpre[0][1], e2 = wpre[0][2];
            fa0.x += a0 + a1 * e1.x + a2 * e2.x;
            fa0.y += a1 * e1.y + a2 * e2.y;
        }
        {
            float2 e1 = wpre[1][1], e2 = wpre[1][2];
            fa1.x += a0 + a1 * e1.x + a2 * e2.x;
            fa1.y += a1 * e1.y + a2 * e2.y;
        }
        FAs[0][d][q] = fa0;
        FAs[1][d][q] = fa1;
        __syncthreads();

        float2 r0 = make_float2(0.f, 0.f), r1 = r0;
        #pragma unroll 8
        for (int t = 0; t < OO; t++) {
            float2 A = FAs[0][d][t];
            float2 h = Hs[0][t][i];
            r0.x += A.x * h.x - A.y * h.y;
            r0.y += A.x * h.y + A.y * h.x;
            float2 B = FAs[1][d][t];
            float2 g = Hs[1][t][i];
            r1.x += B.x * g.x - B.y * g.y;
            r1.y += B.x * g.y + B.y * g.x;
        }
        g_Wh[f0][d][i]     = __floats2half2_rn(r0.x, r0.y);
        g_Wh[f0 + 1][d][i] = __floats2half2_rn(r1.x, r1.y);
    } else {
        // ---- fix role: exact y for t < TFIX, batch b; 1024 threads = (t, o).
        //      s-loop is warp-uniform (t = tid>>5); g_Fs read directly from
        //      global (coalesced, L2-shared across the 32 fix blocks).
        float* u     = reinterpret_cast<float*>(raw);            // 1024 f
        float* delta = u + TFIX * DD;                            // 1024 f
        float* M1t   = delta + TFIX * OO;                        // 1024 f
        float* M2t   = M1t + OO * OO;                            // 1024 f
        float* mu    = M2t + OO * OO;                            // 3072 f
        float* y1    = mu + 3 * DD * OO;                         // 32 f
        float* y2    = y1 + OO;                                  // 32 f  (29 KB)
        int b = blk - FH / 2;
        int t = tid >> 5, o = tid & 31;
        u[tid] = inp[(size_t)b * LSEQ * DD + tid];               // TFIX*DD = 1024
        {
            int i = tid >> 5, oo = tid & 31;                     // OO*OO = 1024
            M1t[i * 32 + oo] = m_y[oo * 64 + i];
            M2t[i * 32 + oo] = m_y[oo * 64 + 32 + i];
        }
        for (int idx = tid; idx < 3 * DD * OO; idx += 1024) {
            int j = idx % 3;
            int rem = idx / 3;          // o*32 + i
            int i = rem & 31;
            int oo = rem >> 5;
            mu[j * (DD * OO) + i * 32 + oo] = m_u[idx];
        }
        __syncthreads();
        float a = 0.f;
        #pragma unroll
        for (int j = 0; j < 3; j++) {
            if (t >= j) {
                const float* mj = &mu[j * (DD * OO)];
                const float* ur = &u[(t - j) * DD];
                #pragma unroll
                for (int i = 0; i < DD; i++)
                    a += mj[i * 32 + o] * ur[i];
            }
        }
        for (int s = 0; s <= t; s++) {                           // warp-uniform bound
            const float* fp = &g_Fs[s][0][0];
            const float* ur = &u[(t - s) * DD];
            #pragma unroll
            for (int d = 0; d < DD; d++)
                a += ur[d] * __ldg(&fp[d * OO + o]);
        }
        delta[tid] = a;
        __syncthreads();
        if (tid < OO) {
            int oo = tid;
            y1[oo] = 0.f; y2[oo] = 0.f;
            __syncwarp();
            for (int tt = 0; tt < TFIX; tt++) {
                float acc = delta[tt * OO + oo];
                #pragma unroll
                for (int i = 0; i < OO; i++)
                    acc += M1t[i * 32 + oo] * y1[i] + M2t[i * 32 + oo] * y2[i];
                __syncwarp();
                y2[oo] = y1[oo];
                __syncwarp();
                y1[oo] = acc;
                __syncwarp();
                out[((size_t)(b * LSEQ + tt)) * OO + oo] = acc;
            }
        }
    }
}

// ---------------- launch 4: per-bin complex matvec G = U * W (profiled) ------
__global__ void k_mul() {
    __shared__ __align__(16) float2 Us[BB][4][DD + 2];   // ~34.8 KB
    int tid = threadIdx.x;            // 256
    int f0 = blockIdx.x * 4;
    #pragma unroll
    for (int k = 0; k < 4; k++) {
        int pair = tid + k * 256;     // pair = b*32 + d
        int b = pair >> 5, d = pair & 31;
        uint4 rw = *reinterpret_cast<const uint4*>(&g_Uh[b][d][f0]);
        __half2 h0 = *reinterpret_cast<__half2*>(&rw.x);
        __half2 h1 = *reinterpret_cast<__half2*>(&rw.y);
        __half2 h2 = *reinterpret_cast<__half2*>(&rw.z);
        __half2 h3 = *reinterpret_cast<__half2*>(&rw.w);
        Us[b][0][d] = __half22float2(h0);
        Us[b][1][d] = __half22float2(h1);
        Us[b][2][d] = __half22float2(h2);
        Us[b][3][d] = __half22float2(h3);
    }
    int bh = tid >> 7;
    int o  = (tid >> 2) & 31;
    int fi = tid & 3;
    int f  = f0 + fi;
    float2 Wreg[DD];
    #pragma unroll
    for (int d = 0; d < DD; d++) Wreg[d] = __half22float2(g_Wh[f][d][o]);
    __syncthreads();
    for (int bi = 0; bi < 16; bi++) {
        int b = bh * 16 + bi;
        float2 a0 = make_float2(0.f, 0.f), a1 = a0;
        const float4* up = reinterpret_cast<const float4*>(&Us[b][fi][0]);
        #pragma unroll
        for (int d2 = 0; d2 < DD / 2; d2++) {
            float4 uv = up[d2];
            float2 w0 = Wreg[2 * d2], w1 = Wreg[2 * d2 + 1];
            a0.x += uv.x * w0.x - uv.y * w0.y;
            a0.y += uv.x * w0.y + uv.y * w0.x;
            a1.x += uv.z * w1.x - uv.w * w1.y;
            a1.y += uv.z * w1.y + uv.w * w1.x;
        }
        g_Gh[b][o][f] = __floats2half2_rn(a0.x + a1.x, a0.y + a1.y);
    }
}

// ---------------- launch 5: inverse FFT (radix-16, 256 thr) ------------------
__global__ void k_ifft(float* __restrict__ out) {
    __shared__ __align__(16) float2 sh[FFT_SH];
    int blk = blockIdx.x;                   // 512: (b, opair)
    int b = blk >> 4, op = blk & 15;
    int tid = threadIdx.x;                  // 256
    #pragma unroll
    for (int rr = 0; rr < 8; rr++) {
        int f = tid + rr * 256;             // 0..2047
        float2 a = __half22float2(g_Gh[b][2 * op][f]);
        float2 c = __half22float2(g_Gh[b][2 * op + 1][f]);
        sh[PHYS(f)] = make_float2(a.x - c.y, a.y + c.x);
        if (f > 0)
            sh[PHYS(NFFT - f)] = make_float2(a.x + c.y, c.x - a.y);
    }
    if (tid == 0) {
        float2 a = __half22float2(g_Gh[b][2 * op][2048]);
        float2 c = __half22float2(g_Gh[b][2 * op + 1][2048]);
        sh[PHYS(2048)] = make_float2(a.x - c.y, a.y + c.x);
    }
    fft16(sh, 1);
    const float inv = 1.f / (float)NFFT;
    for (int t = tid; t < LSEQ; t += 256) {
        if (t < TFIX) continue;             // fix (launch 3) owns these
        float2 z = sh[PHYS(t)];
        float2* p = reinterpret_cast<float2*>(out + ((size_t)(b * LSEQ + t)) * OO + 2 * op);
        *p = make_float2(z.x * inv, z.y * inv);
    }
}

// ---------------- launch ------------------------------------------------------
extern "C" void kernel_launch(void* const* d_in, const int* in_sizes, int n_in,
                              void* d_out, int out_size) {
    const float* inputs  = (const float*)d_in[0];
    const float* eigvals = (const float*)d_in[1];
    const float* eigvecs = (const float*)d_in[2];
    const float* m_u     = (const float*)d_in[3];
    const float* m_phi   = (const float*)d_in[4];
    const float* m_y     = (const float*)d_in[5];
    float* out = (float*)d_out;

    k_pre  <<<53, 1024>>>(m_y, eigvals, eigvecs, m_phi);                  // launch 1
    k_fwd  <<<512, 256>>>(inputs);                                        // launch 2
    k_Wfix <<<FH / 2 + BB, 1024>>>(eigvals, m_phi, m_u, inputs, m_y, out);// launch 3
    k_mul  <<<FH / 4, 256>>>();                                           // launch 4 (profiled)
    k_ifft <<<BB * OO / 2, 256>>>(out);                                   // launch 5
}

// round 17
// speedup vs baseline: 1.4224x; 1.0477x over previous
#include <cuda_runtime.h>
#include <cuda_fp16.h>
#include <math.h>

#define NFFT  4096
#define LOGN  12
#define LSEQ  2048
#define BB    32
#define DD    32
#define KK    32
#define OO    32
#define JH    24      // truncated impulse-response length of y-recurrence
#define FH    2064    // padded half-spectrum bin count (>= 2049)
#define TFIX  32      // first TFIX timesteps recomputed exactly (alias reaches t<=22)

// padded shared-FFT addressing
#define PHYS(i) ((i) + ((i) >> 2))
#define FFT_SH  (NFFT + NFFT / 4)   // 5120 float2 = 40 KB

// ---------------- scratch (device globals; no allocation allowed) ------------
__device__ __half2 g_Uh[BB][DD][FH];   // FFT of inputs (fp16)   (b, d, f<=half)
__device__ __half2 g_Gh[BB][OO][FH];   // output spectra (fp16)  (b, o, f<=half)
__device__ __half2 g_Wh[FH][DD][OO];   // combined filter (fp16) (f<=half, d, o)
__device__ float2  g_V[KK][FH];        // FFT of eig_vecs        (k, f<=half)
__device__ float   g_h[JH][OO][OO];    // impulse response of recurrence
__device__ float   g_Fs[TFIX][DD][OO]; // time-domain F for the fixup region
__device__ float2  g_tw[NFFT];         // twiddles, per-stage layout [half + p]

// ---------------- helpers ----------------------------------------------------
__device__ __forceinline__ float2 cmulf(float2 a, float2 b) {
    return make_float2(a.x*b.x - a.y*b.y, a.x*b.y + a.y*b.x);
}

__device__ __forceinline__ void bfly4(float2& A, float2& B, float2& C, float2& D,
                                      int inverse) {
    float2 t0 = make_float2(A.x + C.x, A.y + C.y);
    float2 t1 = make_float2(A.x - C.x, A.y - C.y);
    float2 t2 = make_float2(B.x + D.x, B.y + D.y);
    float2 t3 = make_float2(B.x - D.x, B.y - D.y);
    A = make_float2(t0.x + t2.x, t0.y + t2.y);
    C = make_float2(t0.x - t2.x, t0.y - t2.y);
    if (!inverse) {
        B = make_float2(t1.x + t3.y, t1.y - t3.x);
        D = make_float2(t1.x - t3.y, t1.y + t3.x);
    } else {
        B = make_float2(t1.x - t3.y, t1.y + t3.x);
        D = make_float2(t1.x + t3.y, t1.y - t3.x);
    }
}

// Radix-16 FFT over 4096 complex values in PADDED shared memory (element i at
// x[PHYS(i)], natural order). 256 threads; 16 elements/thread; 3 shared rounds.
// The __syncthreads() between gather and scatter in pair 0 is load-bearing.
__device__ void fft16(float2* x, int inverse) {
    int tid = threadIdx.x;   // 256
    __syncthreads();
    // ---- pair 0: stages q=1 and q=4; reads digit-reversed, writes 16t+j ----
    {
        int revT = ((tid & 3) << 6) | (((tid >> 2) & 3) << 4)
                 | (((tid >> 4) & 3) << 2) | ((tid >> 6) & 3);
        float2 v[16];
        #pragma unroll
        for (int j = 0; j < 16; j++) {
            int src = revT + ((j >> 2) << 8) + ((j & 3) << 10);
            v[j] = x[PHYS(src)];
        }
        __syncthreads();   // all gathers complete before any scatter
        #pragma unroll
        for (int c = 0; c < 4; c++)
            bfly4(v[4*c], v[4*c+1], v[4*c+2], v[4*c+3], inverse);
        #pragma unroll
        for (int c = 0; c < 4; c++) {
            float2 w1 = __ldg(&g_tw[8 + c]);
            float2 w2 = __ldg(&g_tw[4 + c]);
            if (inverse) { w1.y = -w1.y; w2.y = -w2.y; }
            float2 w3 = cmulf(w1, w2);
            v[c+4]  = cmulf(v[c+4],  w1);
            v[c+8]  = cmulf(v[c+8],  w2);
            v[c+12] = cmulf(v[c+12], w3);
            bfly4(v[c], v[c+4], v[c+8], v[c+12], inverse);
        }
        int base = tid << 4;
        #pragma unroll
        for (int j = 0; j < 16; j++) x[PHYS(base + j)] = v[j];
    }
    __syncthreads();
    // ---- pair 1: stages q=16 and q=64 ----------------------------------------
    {
        int p = tid & 15;
        int base = ((tid >> 4) << 8) | p;
        float2 v[16];
        #pragma unroll
        for (int j = 0; j < 16; j++) v[j] = x[PHYS(base + j * 16)];
        float2 w1 = __ldg(&g_tw[32 + p]);
        float2 w2 = __ldg(&g_tw[16 + p]);
        if (inverse) { w1.y = -w1.y; w2.y = -w2.y; }
        float2 w3 = cmulf(w1, w2);
        #pragma unroll
        for (int c = 0; c < 4; c++) {
            v[4*c+1] = cmulf(v[4*c+1], w1);
            v[4*c+2] = cmulf(v[4*c+2], w2);
            v[4*c+3] = cmulf(v[4*c+3], w3);
            bfly4(v[4*c], v[4*c+1], v[4*c+2], v[4*c+3], inverse);
        }
        #pragma unroll
        for (int c = 0; c < 4; c++) {
            int pc = p + c * 16;
            float2 u1 = __ldg(&g_tw[128 + pc]);
            float2 u2 = __ldg(&g_tw[64 + pc]);
            if (inverse) { u1.y = -u1.y; u2.y = -u2.y; }
            float2 u3 = cmulf(u1, u2);
            v[c+4]  = cmulf(v[c+4],  u1);
            v[c+8]  = cmulf(v[c+8],  u2);
            v[c+12] = cmulf(v[c+12], u3);
            bfly4(v[c], v[c+4], v[c+8], v[c+12], inverse);
        }
        #pragma unroll
        for (int j = 0; j < 16; j++) x[PHYS(base + j * 16)] = v[j];
    }
    __syncthreads();
    // ---- pair 2: stages q=256 and q=1024 -------------------------------------
    {
        int p = tid;
        float2 v[16];
        #pragma unroll
        for (int j = 0; j < 16; j++) v[j] = x[PHYS(p + j * 256)];
        float2 w1 = __ldg(&g_tw[512 + p]);
        float2 w2 = __ldg(&g_tw[256 + p]);
        if (inverse) { w1.y = -w1.y; w2.y = -w2.y; }
        float2 w3 = cmulf(w1, w2);
        #pragma unroll
        for (int c = 0; c < 4; c++) {
            v[4*c+1] = cmulf(v[4*c+1], w1);
            v[4*c+2] = cmulf(v[4*c+2], w2);
            v[4*c+3] = cmulf(v[4*c+3], w3);
            bfly4(v[4*c], v[4*c+1], v[4*c+2], v[4*c+3], inverse);
        }
        #pragma unroll
        for (int c = 0; c < 4; c++) {
            int pc = p + c * 256;
            float2 u1 = __ldg(&g_tw[2048 + pc]);
            float2 u2 = __ldg(&g_tw[1024 + pc]);
            if (inverse) { u1.y = -u1.y; u2.y = -u2.y; }
            float2 u3 = cmulf(u1, u2);
            v[c+4]  = cmulf(v[c+4],  u1);
            v[c+8]  = cmulf(v[c+8],  u2);
            v[c+12] = cmulf(v[c+12], u3);
            bfly4(v[c], v[c+4], v[c+8], v[c+12], inverse);
        }
        #pragma unroll
        for (int j = 0; j < 16; j++) x[PHYS(p + j * 256)] = v[j];
    }
    __syncthreads();
}

// ---------------- launch 1: twiddles + h-recurrence + Fs (256 thr) -----------
// blocks 0..3: g_tw (1024 entries each); block 4: g_h; blocks 5..36: g_Fs
__global__ void k_pre(const float* __restrict__ m_y,
                      const float* __restrict__ eig_vals,
                      const float* __restrict__ ev,
                      const float* __restrict__ m_phi) {
    __shared__ __align__(16) float shf[4 * OO * OO];   // 16 KB
    int blk = blockIdx.x;
    int tid = threadIdx.x;                  // 256
    if (blk < 4) {
        #pragma unroll
        for (int k = 0; k < 4; k++) {
            int i = blk * 1024 + tid + k * 256;
            if (i == 0) { g_tw[0] = make_float2(1.f, 0.f); continue; }
            int s = 31 - __clz(i);
            int half = 1 << s;
            int p = i - half;
            float ang = -3.14159265358979323846f * (float)p / (float)half;
            float sn, cs; sincosf(ang, &sn, &cs);
            g_tw[i] = make_float2(cs, sn);
        }
    } else if (blk == 4) {
        float* M1  = shf;
        float* M2  = M1 + OO * OO;
        float* hp  = M2 + OO * OO;
        float* hp2 = hp + OO * OO;
        #pragma unroll
        for (int r = 0; r < 4; r++) {
            int idx = tid + r * 256;
            int o = idx >> 5, i = idx & 31;
            M1[idx] = m_y[o * 64 + i];
            M2[idx] = m_y[o * 64 + 32 + i];
            float h0 = (o == i) ? 1.f : 0.f;
            hp2[idx] = h0;
            g_h[0][o][i] = h0;
            hp[idx] = m_y[o * 64 + i];
            g_h[1][o][i] = m_y[o * 64 + i];
        }
        __syncthreads();
        for (int j = 2; j < JH; j++) {
            float acc[4];
            #pragma unroll
            for (int r = 0; r < 4; r++) {
                int idx = tid + r * 256;
                int o = idx >> 5, i = idx & 31;
                float a = 0.f;
                #pragma unroll
                for (int t = 0; t < 32; t++)
                    a += M1[o * 32 + t] * hp[t * 32 + i] + M2[o * 32 + t] * hp2[t * 32 + i];
                acc[r] = a;
            }
            __syncthreads();
            #pragma unroll
            for (int r = 0; r < 4; r++) { int idx = tid + r * 256; hp2[idx] = hp[idx]; }
            __syncthreads();
            #pragma unroll
            for (int r = 0; r < 4; r++) {
                int idx = tid + r * 256;
                int o = idx >> 5, i = idx & 31;
                hp[idx] = acc[r];
                g_h[j][o][i] = acc[r];
            }
            __syncthreads();
        }
    } else {
        float* sc = shf;
        float* vv = sc + KK;
        int s = blk - 5;                    // 0..TFIX-1
        if (tid < KK) {
            sc[tid] = sqrtf(sqrtf(eig_vals[tid]));
            vv[tid] = ev[(size_t)s * KK + tid];
        }
        __syncthreads();
        #pragma unroll
        for (int r = 0; r < 4; r++) {
            int idx = tid + r * 256;
            int d = idx >> 5, o = idx & 31;
            float acc = 0.f;
            #pragma unroll
            for (int k = 0; k < KK; k++)
                acc += sc[k] * vv[k] * m_phi[(k * DD + d) * OO + o];
            g_Fs[s][d][o] = acc;
        }
    }
}

// ---------------- launch 2: forward FFTs (inputs + eig_vecs, radix-16) -------
// blocks 0..511: inputs (b = blk>>4, dpair = blk&15); blocks 512..527: eig_vecs
__global__ void k_fwd(const float* __restrict__ inp,
                      const float* __restrict__ ev) {
    __shared__ __align__(16) float2 sh[FFT_SH];
    int blk = blockIdx.x;
    int tid = threadIdx.x;                  // 256
    if (blk < 512) {
        int b = blk >> 4, dp = blk & 15;
        #pragma unroll
        for (int rr = 0; rr < 8; rr++) {
            int t = tid + rr * 256;
            const float2 v = *reinterpret_cast<const float2*>(
                inp + ((size_t)(b * LSEQ + t)) * DD + 2 * dp);
            sh[PHYS(t)] = v;
        }
        #pragma unroll
        for (int rr = 0; rr < 8; rr++) {
            int t = LSEQ + tid + rr * 256;
            sh[PHYS(t)] = make_float2(0.f, 0.f);
        }
        fft16(sh, 0);
        for (int f = tid; f < FH; f += 256) {
            float2 zf = sh[PHYS(f)];
            int m = (NFFT - f) & (NFFT - 1);
            float2 zm = sh[PHYS(m)];
            g_Uh[b][2 * dp][f]     = __floats2half2_rn(0.5f * (zf.x + zm.x), 0.5f * (zf.y - zm.y));
            g_Uh[b][2 * dp + 1][f] = __floats2half2_rn(0.5f * (zf.y + zm.y), 0.5f * (zm.x - zf.x));
        }
    } else {
        int kp = blk - 512;                 // 0..15 -> filters 2kp, 2kp+1
        #pragma unroll
        for (int rr = 0; rr < 8; rr++) {
            int t = tid + rr * 256;
            const float2 v = *reinterpret_cast<const float2*>(ev + (size_t)t * KK + 2 * kp);
            sh[PHYS(t)] = v;
        }
        #pragma unroll
        for (int rr = 0; rr < 8; rr++) {
            int t = LSEQ + tid + rr * 256;
            sh[PHYS(t)] = make_float2(0.f, 0.f);
        }
        fft16(sh, 0);
        for (int f = tid; f < FH; f += 256) {
            float2 zf = sh[PHYS(f)];
            int m = (NFFT - f) & (NFFT - 1);
            float2 zm = sh[PHYS(m)];
            g_V[2 * kp][f]     = make_float2(0.5f * (zf.x + zm.x), 0.5f * (zf.y - zm.y));
            g_V[2 * kp + 1][f] = make_float2(0.5f * (zf.y + zm.y), 0.5f * (zm.x - zf.x));
        }
    }
}

// ---------------- launch 3: combined filter W + exact fixup ------------------
// blocks 0..1031: k_W (2 bins/block); blocks 1032..1063: fix (batch b)
__global__ void k_Wfix(const float* __restrict__ eig_vals,
                       const float* __restrict__ m_phi,
                       const float* __restrict__ m_u,
                       const float* __restrict__ inp,
                       const float* __restrict__ m_y,
                       float* __restrict__ out) {
    __shared__ __align__(16) char raw[35840];   // 35 KB union
    int blk = blockIdx.x;
    int tid = threadIdx.x;                  // 1024
    if (blk < FH / 2) {
        float2 (*Hs)[OO][OO + 1] = reinterpret_cast<float2(*)[OO][OO + 1]>(raw);       // 16896 B
        float2 (*FAs)[DD][OO]    = reinterpret_cast<float2(*)[DD][OO]>(raw + 16896);   // 16384 B
        float2 (*sv)[KK]         = reinterpret_cast<float2(*)[KK]>(raw + 33280);       // 512 B
        float2 (*wpre)[JH]       = reinterpret_cast<float2(*)[JH]>(raw + 33792);       // 384 B
        int f0 = blk * 2;
        int o = tid >> 5, i = tid & 31;

        if (tid < 2 * JH) {
            int bin = tid >= JH ? 1 : 0;
            int j = tid - bin * JH;
            float ang = -6.283185307179586f * (float)(f0 + bin) * (float)j / (float)NFFT;
            float sn, cs; sincosf(ang, &sn, &cs);
            wpre[bin][j] = make_float2(cs, sn);
        }
        if (tid >= 64 && tid < 128) {
            int bin = (tid - 64) >> 5, k = tid & 31;
            float sc = sqrtf(sqrtf(eig_vals[k]));
            float2 v = g_V[k][f0 + bin];
            sv[bin][k] = make_float2(v.x * sc, v.y * sc);
        }
        __syncthreads();

        float2 acc0 = make_float2(0.f, 0.f), acc1 = acc0;
        #pragma unroll 4
        for (int j = 0; j < JH; j++) {
            float hv = g_h[j][o][i];
            float2 w0j = wpre[0][j];
            float2 w1j = wpre[1][j];
            acc0.x += hv * w0j.x; acc0.y += hv * w0j.y;
            acc1.x += hv * w1j.x; acc1.y += hv * w1j.y;
        }
        Hs[0][i][o] = acc0;
        Hs[1][i][o] = acc1;

        int d = o, q = i;
        float2 fa0 = make_float2(0.f, 0.f), fa1 = fa0;
        #pragma unroll 8
        for (int k = 0; k < KK; k++) {
            float m = m_phi[(k * DD + d) * OO + q];
            fa0.x += sv[0][k].x * m; fa0.y += sv[0][k].y * m;
            fa1.x += sv[1][k].x * m; fa1.y += sv[1][k].y * m;
        }
        float a0 = m_u[(q * DD + d) * 3 + 0];
        float a1 = m_u[(q * DD + d) * 3 + 1];
        float a2 = m_u[(q * DD + d) * 3 + 2];
        {
            float2 e1 = wpre[0][1], e2 = wpre[0][2];
            fa0.x += a0 + a1 * e1.x + a2 * e2.x;
            fa0.y += a1 * e1.y + a2 * e2.y;
        }
        {
            float2 e1 = wpre[1][1], e2 = wpre[1][2];
            fa1.x += a0 + a1 * e1.x + a2 * e2.x;
            fa1.y += a1 * e1.y + a2 * e2.y;
        }
        FAs[0][d][q] = fa0;
        FAs[1][d][q] = fa1;
        __syncthreads();

        float2 r0 = make_float2(0.f, 0.f), r1 = r0;
        #pragma unroll 8
        for (int t = 0; t < OO; t++) {
            float2 A = FAs[0][d][t];
            float2 h = Hs[0][t][i];
            r0.x += A.x * h.x - A.y * h.y;
            r0.y += A.x * h.y + A.y * h.x;
            float2 B = FAs[1][d][t];
            float2 g = Hs[1][t][i];
            r1.x += B.x * g.x - B.y * g.y;
            r1.y += B.x * g.y + B.y * g.x;
        }
        g_Wh[f0][d][i]     = __floats2half2_rn(r0.x, r0.y);
        g_Wh[f0 + 1][d][i] = __floats2half2_rn(r1.x, r1.y);
    } else {
        // ---- fix role: exact y for t < TFIX, batch b; 1024 threads = (t, o)
        float* u     = reinterpret_cast<float*>(raw);            // 1024 f
        float* delta = u + TFIX * DD;                            // 1024 f
        float* M1t   = delta + TFIX * OO;                        // 1024 f
        float* M2t   = M1t + OO * OO;                            // 1024 f
        float* mu    = M2t + OO * OO;                            // 3072 f
        float* y1    = mu + 3 * DD * OO;                         // 32 f
        float* y2    = y1 + OO;                                  // 32 f
        int b = blk - FH / 2;
        int t = tid >> 5, o = tid & 31;
        u[tid] = inp[(size_t)b * LSEQ * DD + tid];
        {
            int i = tid >> 5, oo = tid & 31;
            M1t[i * 32 + oo] = m_y[oo * 64 + i];
            M2t[i * 32 + oo] = m_y[oo * 64 + 32 + i];
        }
        for (int idx = tid; idx < 3 * DD * OO; idx += 1024) {
            int j = idx % 3;
            int rem = idx / 3;
            int i = rem & 31;
            int oo = rem >> 5;
            mu[j * (DD * OO) + i * 32 + oo] = m_u[idx];
        }
        __syncthreads();
        float a = 0.f;
        #pragma unroll
        for (int j = 0; j < 3; j++) {
            if (t >= j) {
                const float* mj = &mu[j * (DD * OO)];
                const float* ur = &u[(t - j) * DD];
                #pragma unroll
                for (int i = 0; i < DD; i++)
                    a += mj[i * 32 + o] * ur[i];
            }
        }
        for (int s = 0; s <= t; s++) {
            const float* fp = &g_Fs[s][0][0];
            const float* ur = &u[(t - s) * DD];
            #pragma unroll
            for (int d = 0; d < DD; d++)
                a += ur[d] * __ldg(&fp[d * OO + o]);
        }
        delta[tid] = a;
        __syncthreads();
        if (tid < OO) {
            int oo = tid;
            y1[oo] = 0.f; y2[oo] = 0.f;
            __syncwarp();
            for (int tt = 0; tt < TFIX; tt++) {
                float acc = delta[tt * OO + oo];
                #pragma unroll
                for (int i = 0; i < OO; i++)
                    acc += M1t[i * 32 + oo] * y1[i] + M2t[i * 32 + oo] * y2[i];
                __syncwarp();
                y2[oo] = y1[oo];
                __syncwarp();
                y1[oo] = acc;
                __syncwarp();
                out[((size_t)(b * LSEQ + tt)) * OO + oo] = acc;
            }
        }
    }
}

// ---------------- launch 4: per-bin complex matvec G = U * W -----------------
__global__ void k_mul() {
    __shared__ __align__(16) float2 Us[BB][4][DD + 2];   // ~34.8 KB
    int tid = threadIdx.x;            // 256
    int f0 = blockIdx.x * 4;
    #pragma unroll
    for (int k = 0; k < 4; k++) {
        int pair = tid + k * 256;     // pair = b*32 + d
        int b = pair >> 5, d = pair & 31;
        uint4 rw = *reinterpret_cast<const uint4*>(&g_Uh[b][d][f0]);
        __half2 h0 = *reinterpret_cast<__half2*>(&rw.x);
        __half2 h1 = *reinterpret_cast<__half2*>(&rw.y);
        __half2 h2 = *reinterpret_cast<__half2*>(&rw.z);
        __half2 h3 = *reinterpret_cast<__half2*>(&rw.w);
        Us[b][0][d] = __half22float2(h0);
        Us[b][1][d] = __half22float2(h1);
        Us[b][2][d] = __half22float2(h2);
        Us[b][3][d] = __half22float2(h3);
    }
    int bh = tid >> 7;
    int o  = (tid >> 2) & 31;
    int fi = tid & 3;
    int f  = f0 + fi;
    float2 Wreg[DD];
    #pragma unroll
    for (int d = 0; d < DD; d++) Wreg[d] = __half22float2(g_Wh[f][d][o]);
    __syncthreads();
    for (int bi = 0; bi < 16; bi++) {
        int b = bh * 16 + bi;
        float2 a0 = make_float2(0.f, 0.f), a1 = a0;
        const float4* up = reinterpret_cast<const float4*>(&Us[b][fi][0]);
        #pragma unroll
        for (int d2 = 0; d2 < DD / 2; d2++) {
            float4 uv = up[d2];
            float2 w0 = Wreg[2 * d2], w1 = Wreg[2 * d2 + 1];
            a0.x += uv.x * w0.x - uv.y * w0.y;
            a0.y += uv.x * w0.y + uv.y * w0.x;
            a1.x += uv.z * w1.x - uv.w * w1.y;
            a1.y += uv.z * w1.y + uv.w * w1.x;
        }
        g_Gh[b][o][f] = __floats2half2_rn(a0.x + a1.x, a0.y + a1.y);
    }
}

// ---------------- launch 5: inverse FFT (radix-16, 256 thr) ------------------
__global__ void k_ifft(float* __restrict__ out) {
    __shared__ __align__(16) float2 sh[FFT_SH];
    int blk = blockIdx.x;                   // 512: (b, opair)
    int b = blk >> 4, op = blk & 15;
    int tid = threadIdx.x;                  // 256
    #pragma unroll
    for (int rr = 0; rr < 8; rr++) {
        int f = tid + rr * 256;             // 0..2047
        float2 a = __half22float2(g_Gh[b][2 * op][f]);
        float2 c = __half22float2(g_Gh[b][2 * op + 1][f]);
        sh[PHYS(f)] = make_float2(a.x - c.y, a.y + c.x);
        if (f > 0)
            sh[PHYS(NFFT - f)] = make_float2(a.x + c.y, c.x - a.y);
    }
    if (tid == 0) {
        float2 a = __half22float2(g_Gh[b][2 * op][2048]);
        float2 c = __half22float2(g_Gh[b][2 * op + 1][2048]);
        sh[PHYS(2048)] = make_float2(a.x - c.y, a.y + c.x);
    }
    fft16(sh, 1);
    const float inv = 1.f / (float)NFFT;
    for (int t = tid; t < LSEQ; t += 256) {
        if (t < TFIX) continue;             // fix (launch 3) owns these
        float2 z = sh[PHYS(t)];
        float2* p = reinterpret_cast<float2*>(out + ((size_t)(b * LSEQ + t)) * OO + 2 * op);
        *p = make_float2(z.x * inv, z.y * inv);
    }
}

// ---------------- launch ------------------------------------------------------
extern "C" void kernel_launch(void* const* d_in, const int* in_sizes, int n_in,
                              void* d_out, int out_size) {
    const float* inputs  = (const float*)d_in[0];
    const float* eigvals = (const float*)d_in[1];
    const float* eigvecs = (const float*)d_in[2];
    const float* m_u     = (const float*)d_in[3];
    const float* m_phi   = (const float*)d_in[4];
    const float* m_y     = (const float*)d_in[5];
    float* out = (float*)d_out;

    k_pre  <<<5 + TFIX, 256>>>(m_y, eigvals, eigvecs, m_phi);             // launch 1
    k_fwd  <<<512 + KK / 2, 256>>>(inputs, eigvecs);                      // launch 2
    k_Wfix <<<FH / 2 + BB, 1024>>>(eigvals, m_phi, m_u, inputs, m_y, out);// launch 3
    k_mul  <<<FH / 4, 256>>>();                                           // launch 4
    k_ifft <<<BB * OO / 2, 256>>>(out);                                   // launch 5
}